// round 1
// baseline (speedup 1.0000x reference)
#include <cuda_runtime.h>
#include <math.h>

#define DEPTH 4
#define DIM 512
#define HEADS 8
#define HD 64
#define MLPD 2048
#define SE_H 32
#define BB 8
#define NSEQ 1024
#define ROWS (BB*NSEQ)
#define EPS 1e-5f
#define ATT_SCALE 0.04419417382415922f  /* 512^-0.5 */

// ---------------- scratch (static device memory, no allocs) ----------------
__device__ float g_x[ROWS*DIM];
__device__ float g_res[ROWS*DIM];
__device__ float g_xn[ROWS*DIM];
__device__ float g_qkv[ROWS*3*DIM];
__device__ float g_scores[(size_t)BB*HEADS*NSEQ*NSEQ]; // 268 MB
__device__ float g_attn[ROWS*DIM];
__device__ float g_h1[ROWS*MLPD];
__device__ float g_h2[ROWS*MLPD];
__device__ float g_pavg[BB*DIM];
__device__ float g_pmax[BB*DIM];
__device__ float g_scale[BB*DIM];

__device__ __forceinline__ float gelu_f(float v){
    return 0.5f * v * (1.0f + erff(v * 0.7071067811865476f));
}

// ---------------- LayerNorm: one block (128 thr) per row of 512 -------------
__global__ void ln_kernel(const float* __restrict__ x, const float* __restrict__ g,
                          const float* __restrict__ bta, float* __restrict__ o){
    int row = blockIdx.x;
    int t = threadIdx.x;
    const float* xr = x + (size_t)row * DIM;
    float v[4];
    float s = 0.f;
#pragma unroll
    for (int i=0;i<4;i++){ v[i] = xr[t + 128*i]; s += v[i]; }
    __shared__ float sh[32];
    for (int off=16;off>0;off>>=1) s += __shfl_down_sync(0xffffffffu, s, off);
    if ((t&31)==0) sh[t>>5] = s;
    __syncthreads();
    if (t < 32){
        float r = (t < 4) ? sh[t] : 0.f;
        for (int off=2;off>0;off>>=1) r += __shfl_down_sync(0xffffffffu, r, off);
        if (t==0) sh[0] = r;
    }
    __syncthreads();
    float mean = sh[0] * (1.0f/DIM);
    __syncthreads();
    float sq = 0.f;
#pragma unroll
    for (int i=0;i<4;i++){ v[i] -= mean; sq += v[i]*v[i]; }
    for (int off=16;off>0;off>>=1) sq += __shfl_down_sync(0xffffffffu, sq, off);
    if ((t&31)==0) sh[t>>5] = sq;
    __syncthreads();
    if (t < 32){
        float r = (t < 4) ? sh[t] : 0.f;
        for (int off=2;off>0;off>>=1) r += __shfl_down_sync(0xffffffffu, r, off);
        if (t==0) sh[0] = r;
    }
    __syncthreads();
    float rstd = rsqrtf(sh[0]*(1.0f/DIM) + EPS);
    float* orow = o + (size_t)row*DIM;
#pragma unroll
    for (int i=0;i<4;i++){
        int c = t + 128*i;
        orow[c] = v[i]*rstd*g[c] + bta[c];
    }
}

// ---------------- Generic batched row-major SGEMM, fused epilogue -----------
// FLAGS: 1 = +bias[col], 2 = gelu, 4 = +residual (R, same layout as C)
template<int BM,int BN,int BK,int TM,int TN,int FLAGS>
__global__ void gemm_nn(const float* __restrict__ A, const float* __restrict__ B,
                        const float* __restrict__ bias, const float* __restrict__ R,
                        float* __restrict__ C,
                        int M, int N, int K, int lda, int ldb, int ldc,
                        long sAb, long sAh, long sBb, long sBh, long sCb, long sCh, int H)
{
    constexpr int THREADS = (BM/TM)*(BN/TN);
    int z = blockIdx.z;
    int zb = z / H, zh = z % H;
    A += (size_t)zb*sAb + (size_t)zh*sAh;
    B += (size_t)zb*sBb + (size_t)zh*sBh;
    C += (size_t)zb*sCb + (size_t)zh*sCh;
    __shared__ float As[BK][BM];
    __shared__ float Bs[BK][BN];
    int t = threadIdx.x;
    int tx = t % (BN/TN);
    int ty = t / (BN/TN);
    int row0 = blockIdx.y * BM;
    int col0 = blockIdx.x * BN;
    float acc[TM][TN];
#pragma unroll
    for (int i=0;i<TM;i++)
#pragma unroll
        for (int j=0;j<TN;j++) acc[i][j]=0.f;

    for (int k0=0;k0<K;k0+=BK){
        for (int i4 = t; i4 < BM*BK/4; i4 += THREADS){
            int r = i4 / (BK/4);
            int c4 = (i4 % (BK/4))*4;
            float4 v = *(const float4*)(A + (size_t)(row0+r)*lda + k0 + c4);
            As[c4+0][r]=v.x; As[c4+1][r]=v.y; As[c4+2][r]=v.z; As[c4+3][r]=v.w;
        }
        for (int i4 = t; i4 < BK*BN/4; i4 += THREADS){
            int r = i4 / (BN/4);
            int c4 = (i4 % (BN/4))*4;
            *(float4*)&Bs[r][c4] = *(const float4*)(B + (size_t)(k0+r)*ldb + col0 + c4);
        }
        __syncthreads();
#pragma unroll
        for (int k=0;k<BK;k++){
            float a[TM], bv[TN];
#pragma unroll
            for (int q=0;q<TM/4;q++) *(float4*)&a[q*4]  = *(const float4*)&As[k][ty*TM+q*4];
#pragma unroll
            for (int q=0;q<TN/4;q++) *(float4*)&bv[q*4] = *(const float4*)&Bs[k][tx*TN+q*4];
#pragma unroll
            for (int i=0;i<TM;i++)
#pragma unroll
                for (int j=0;j<TN;j++) acc[i][j] = fmaf(a[i], bv[j], acc[i][j]);
        }
        __syncthreads();
    }
#pragma unroll
    for (int i=0;i<TM;i++){
        int r = row0 + ty*TM + i;
#pragma unroll
        for (int j=0;j<TN;j++){
            int c = col0 + tx*TN + j;
            float v = acc[i][j];
            if (FLAGS & 1) v += bias[c];
            if (FLAGS & 2) v = gelu_f(v);
            if (FLAGS & 4) v += R[(size_t)r*ldc + c];
            C[(size_t)r*ldc + c] = v;
        }
    }
}

// ---------------- Attention scores: S = Q K^T * scale, per (b,h) ------------
__global__ void attn_scores_kernel(const float* __restrict__ qkv, float* __restrict__ S){
    int z = blockIdx.z;
    int bb = z / HEADS, hh = z % HEADS;
    const float* Q  = qkv + (size_t)bb*NSEQ*3*DIM + hh*HD;
    const float* Kp = Q + DIM;
    float* Sp = S + (size_t)z*NSEQ*NSEQ;
    __shared__ float Qs[HD][64];
    __shared__ float Ks[HD][64];
    int t = threadIdx.x;
    int tx = t % 16, ty = t / 16;
    int i0 = blockIdx.y*64, j0 = blockIdx.x*64;
    for (int idx = t; idx < 64*16; idx += 256){
        int r = idx / 16;
        int c4 = (idx % 16)*4;
        float4 v = *(const float4*)(Q  + (size_t)(i0+r)*(3*DIM) + c4);
        Qs[c4+0][r]=v.x; Qs[c4+1][r]=v.y; Qs[c4+2][r]=v.z; Qs[c4+3][r]=v.w;
        float4 w = *(const float4*)(Kp + (size_t)(j0+r)*(3*DIM) + c4);
        Ks[c4+0][r]=w.x; Ks[c4+1][r]=w.y; Ks[c4+2][r]=w.z; Ks[c4+3][r]=w.w;
    }
    __syncthreads();
    float acc[4][4] = {};
#pragma unroll
    for (int k=0;k<HD;k++){
        float4 a = *(const float4*)&Qs[k][ty*4];
        float4 b = *(const float4*)&Ks[k][tx*4];
        float av[4]={a.x,a.y,a.z,a.w}, bv[4]={b.x,b.y,b.z,b.w};
#pragma unroll
        for (int i=0;i<4;i++)
#pragma unroll
            for (int j=0;j<4;j++) acc[i][j] = fmaf(av[i], bv[j], acc[i][j]);
    }
#pragma unroll
    for (int i=0;i<4;i++)
#pragma unroll
        for (int j=0;j<4;j++)
            Sp[(size_t)(i0+ty*4+i)*NSEQ + (j0+tx*4+j)] = acc[i][j]*ATT_SCALE;
}

// ---------------- Row softmax over 1024 -------------------------------------
__global__ void softmax_kernel(float* __restrict__ S){
    size_t row = blockIdx.x;
    float* p = S + row*NSEQ;
    int t = threadIdx.x;
    float v[4];
    float m = -1e30f;
#pragma unroll
    for (int i=0;i<4;i++){ v[i] = p[t + 256*i]; m = fmaxf(m, v[i]); }
    __shared__ float sh[32];
    for (int off=16;off>0;off>>=1) m = fmaxf(m, __shfl_down_sync(0xffffffffu,m,off));
    if ((t&31)==0) sh[t>>5]=m;
    __syncthreads();
    if (t<32){
        float r = (t<8)?sh[t]:-1e30f;
        for (int off=4;off>0;off>>=1) r = fmaxf(r, __shfl_down_sync(0xffffffffu,r,off));
        if (t==0) sh[0]=r;
    }
    __syncthreads();
    m = sh[0];
    __syncthreads();
    float s = 0.f;
#pragma unroll
    for (int i=0;i<4;i++){ v[i] = __expf(v[i]-m); s += v[i]; }
    for (int off=16;off>0;off>>=1) s += __shfl_down_sync(0xffffffffu,s,off);
    if ((t&31)==0) sh[t>>5]=s;
    __syncthreads();
    if (t<32){
        float r = (t<8)?sh[t]:0.f;
        for (int off=4;off>0;off>>=1) r += __shfl_down_sync(0xffffffffu,r,off);
        if (t==0) sh[0]=r;
    }
    __syncthreads();
    float inv = 1.0f / sh[0];
#pragma unroll
    for (int i=0;i<4;i++) p[t + 256*i] = v[i]*inv;
}

// ---------------- SE: avg/max pool over tokens ------------------------------
__global__ void pool_kernel(const float* __restrict__ x){
    int bb = blockIdx.x / (DIM/128);
    int ch = (blockIdx.x % (DIM/128))*128 + threadIdx.x;
    const float* p = x + (size_t)bb*NSEQ*DIM + ch;
    float s = 0.f, m = -1e30f;
    for (int n=0;n<NSEQ;n++){ float v = p[(size_t)n*DIM]; s += v; m = fmaxf(m,v); }
    g_pavg[bb*DIM+ch] = s * (1.0f/NSEQ);
    g_pmax[bb*DIM+ch] = m;
}

// ---------------- SE: shared MLP + sigmoid gate -----------------------------
__global__ void semlp_kernel(const float* __restrict__ w1, const float* __restrict__ b1,
                             const float* __restrict__ w2, const float* __restrict__ b2){
    int bb = blockIdx.x;
    int t = threadIdx.x; // 256
    __shared__ float sa[DIM], sm[DIM], ha[SE_H], hm[SE_H];
    sa[t] = g_pavg[bb*DIM+t]; sa[t+256] = g_pavg[bb*DIM+t+256];
    sm[t] = g_pmax[bb*DIM+t]; sm[t+256] = g_pmax[bb*DIM+t+256];
    __syncthreads();
    if (t < SE_H){
        float s = b1[t];
        for (int c=0;c<DIM;c++) s += sa[c]*w1[c*SE_H+t];
        ha[t] = fmaxf(s, 0.f);
    } else if (t < 2*SE_H){
        int j = t - SE_H;
        float s = b1[j];
        for (int c=0;c<DIM;c++) s += sm[c]*w1[c*SE_H+j];
        hm[j] = fmaxf(s, 0.f);
    }
    __syncthreads();
    for (int c=t;c<DIM;c+=256){
        float s = 2.0f*b2[c];
        for (int j=0;j<SE_H;j++) s += (ha[j]+hm[j])*w2[j*DIM+c];
        g_scale[bb*DIM+c] = 1.0f/(1.0f+expf(-s));
    }
}

__global__ void scale_apply_kernel(float* __restrict__ xn){
    int bi = blockIdx.x;
    int t = threadIdx.x; // 512
    int bb = bi >> 10;
    size_t idx = (size_t)bi*DIM + t;
    xn[idx] *= g_scale[bb*DIM + t];
}

// ---------------- Depthwise 3x3 conv over 32x32 grid + bias + gelu ----------
__global__ void dwconv_kernel(const float* __restrict__ h1, const float* __restrict__ w,
                              const float* __restrict__ bias, float* __restrict__ out){
    __shared__ float wsh[256*9];
    int m0 = blockIdx.y*256;
    for (int q=threadIdx.x; q<256*9; q+=256) wsh[q] = w[(size_t)m0*9 + q];
    __syncthreads();
    int bi = blockIdx.x;            // b*NSEQ + n
    int m  = m0 + threadIdx.x;
    int bb = bi >> 10, n = bi & 1023;
    int y = n >> 5, x = n & 31;
    float wv[9];
#pragma unroll
    for (int q=0;q<9;q++) wv[q] = wsh[threadIdx.x*9+q];
    float acc = 0.f;
#pragma unroll
    for (int ky=0;ky<3;ky++){
        int yy = y + ky - 1;
        if (yy < 0 || yy > 31) continue;
#pragma unroll
        for (int kx=0;kx<3;kx++){
            int xx = x + kx - 1;
            if (xx < 0 || xx > 31) continue;
            acc += h1[((size_t)(bb<<10) + (yy<<5) + xx)*MLPD + m] * wv[ky*3+kx];
        }
    }
    out[(size_t)bi*MLPD + m] = gelu_f(acc + bias[m]);
}

// ---------------- skip-merge every 2 layers: x += res; res = x --------------
__global__ void addres_kernel(){
    size_t i = (size_t)blockIdx.x*256 + threadIdx.x;
    float v = g_x[i] + g_res[i];
    g_x[i] = v; g_res[i] = v;
}

// ---------------- host ------------------------------------------------------
extern "C" void kernel_launch(void* const* d_in, const int* in_sizes, int n_in,
                              void* d_out, int out_size){
    const float* x     = (const float*)d_in[0];
    const float* ln1_g = (const float*)d_in[1];
    const float* ln1_b = (const float*)d_in[2];
    const float* w_qkv = (const float*)d_in[3];
    const float* w_out = (const float*)d_in[4];
    const float* b_out = (const float*)d_in[5];
    const float* ln2_g = (const float*)d_in[6];
    const float* ln2_b = (const float*)d_in[7];
    const float* se_w1 = (const float*)d_in[8];
    const float* se_b1 = (const float*)d_in[9];
    const float* se_w2 = (const float*)d_in[10];
    const float* se_b2 = (const float*)d_in[11];
    const float* w1    = (const float*)d_in[12];
    const float* b1    = (const float*)d_in[13];
    const float* dw_w  = (const float*)d_in[14];
    const float* dw_b  = (const float*)d_in[15];
    const float* w2    = (const float*)d_in[16];
    const float* b2    = (const float*)d_in[17];

    float *px,*pres,*pxn,*pqkv,*pS,*pattn,*ph1,*ph2;
    cudaGetSymbolAddress((void**)&px,   g_x);
    cudaGetSymbolAddress((void**)&pres, g_res);
    cudaGetSymbolAddress((void**)&pxn,  g_xn);
    cudaGetSymbolAddress((void**)&pqkv, g_qkv);
    cudaGetSymbolAddress((void**)&pS,   g_scores);
    cudaGetSymbolAddress((void**)&pattn,g_attn);
    cudaGetSymbolAddress((void**)&ph1,  g_h1);
    cudaGetSymbolAddress((void**)&ph2,  g_h2);

    cudaMemcpyAsync(px,   x, (size_t)ROWS*DIM*sizeof(float), cudaMemcpyDeviceToDevice, 0);
    cudaMemcpyAsync(pres, x, (size_t)ROWS*DIM*sizeof(float), cudaMemcpyDeviceToDevice, 0);

    for (int i=0;i<DEPTH;i++){
        // x -> ln1 -> xn
        ln_kernel<<<ROWS,128>>>(px, ln1_g+i*DIM, ln1_b+i*DIM, pxn);
        // qkv = xn @ w_qkv
        gemm_nn<128,128,16,8,8,0><<<dim3(3*DIM/128, ROWS/128, 1), 256>>>(
            pxn, w_qkv+(size_t)i*DIM*3*DIM, nullptr, nullptr, pqkv,
            ROWS, 3*DIM, DIM, DIM, 3*DIM, 3*DIM, 0,0,0,0,0,0, 1);
        // scores + softmax
        attn_scores_kernel<<<dim3(NSEQ/64, NSEQ/64, BB*HEADS), 256>>>(pqkv, pS);
        softmax_kernel<<<BB*HEADS*NSEQ, 256>>>(pS);
        // attn = softmax(S) @ V  (batched over b,h; merged-head output layout)
        gemm_nn<64,64,16,4,4,0><<<dim3(1, NSEQ/64, BB*HEADS), 256>>>(
            pS, pqkv + 2*DIM, nullptr, nullptr, pattn,
            NSEQ, HD, NSEQ, NSEQ, 3*DIM, DIM,
            (long)HEADS*NSEQ*NSEQ, (long)NSEQ*NSEQ,
            (long)NSEQ*3*DIM, (long)HD,
            (long)NSEQ*DIM, (long)HD, HEADS);
        // x = attn @ w_out + b_out + x
        gemm_nn<128,128,16,8,8,5><<<dim3(DIM/128, ROWS/128, 1), 256>>>(
            pattn, w_out+(size_t)i*DIM*DIM, b_out+i*DIM, px, px,
            ROWS, DIM, DIM, DIM, DIM, DIM, 0,0,0,0,0,0, 1);
        // x -> ln2 -> xn
        ln_kernel<<<ROWS,128>>>(px, ln2_g+i*DIM, ln2_b+i*DIM, pxn);
        // SE gate
        pool_kernel<<<BB*(DIM/128),128>>>(pxn);
        semlp_kernel<<<BB,256>>>(se_w1+(size_t)i*DIM*SE_H, se_b1+i*SE_H,
                                 se_w2+(size_t)i*SE_H*DIM, se_b2+i*DIM);
        scale_apply_kernel<<<ROWS,512>>>(pxn);
        // h1 = gelu(xn @ w1 + b1)
        gemm_nn<128,128,16,8,8,3><<<dim3(MLPD/128, ROWS/128, 1),256>>>(
            pxn, w1+(size_t)i*DIM*MLPD, b1+i*MLPD, nullptr, ph1,
            ROWS, MLPD, DIM, DIM, MLPD, MLPD, 0,0,0,0,0,0, 1);
        // h2 = gelu(dwconv3x3(h1) + dw_b)
        dwconv_kernel<<<dim3(ROWS, MLPD/256), 256>>>(ph1, dw_w+(size_t)i*MLPD*9, dw_b+i*MLPD, ph2);
        // x = gelu(h2 @ w2 + b2) + x
        gemm_nn<128,128,16,8,8,7><<<dim3(DIM/128, ROWS/128, 1),256>>>(
            ph2, w2+(size_t)i*MLPD*DIM, b2+i*DIM, px, px,
            ROWS, DIM, MLPD, MLPD, DIM, DIM, 0,0,0,0,0,0, 1);
        // skip merge every 2 layers
        if ((i&1)==1) addres_kernel<<<ROWS*DIM/256, 256>>>();
    }
    cudaMemcpyAsync(d_out, px, (size_t)ROWS*DIM*sizeof(float), cudaMemcpyDeviceToDevice, 0);
}

// round 3
// speedup vs baseline: 1.2640x; 1.2640x over previous
#include <cuda_runtime.h>
#include <math.h>
#include <stdint.h>

#define DEPTH 4
#define DIM 512
#define HEADS 8
#define HD 64
#define MLPD 2048
#define SE_H 32
#define BB 8
#define NSEQ 1024
#define ROWS (BB*NSEQ)
#define EPS 1e-5f
#define ATT_SCALE 0.04419417382415922f  /* 512^-0.5 */

// ---------------- scratch (static device memory, no allocs) ----------------
__device__ float g_x[ROWS*DIM];
__device__ float g_res[ROWS*DIM];
__device__ float g_xn[ROWS*DIM];
__device__ float g_qkv[ROWS*3*DIM];
__device__ float g_scores[(size_t)BB*HEADS*NSEQ*NSEQ]; // 268 MB
__device__ float g_attn[ROWS*DIM];
__device__ float g_h1[ROWS*MLPD];
__device__ float g_h2[ROWS*MLPD];
__device__ float g_pavg[BB*DIM];
__device__ float g_pmax[BB*DIM];
__device__ float g_scale[BB*DIM];

__device__ __forceinline__ float gelu_f(float v){
    return 0.5f * v * (1.0f + erff(v * 0.7071067811865476f));
}

__device__ __forceinline__ uint32_t f2tf32(float f){
    uint32_t u; asm("cvt.rna.tf32.f32 %0, %1;" : "=r"(u) : "f"(f)); return u;
}

__device__ __forceinline__ void mma_tf32(float* d, const uint32_t* a, const uint32_t* b){
    asm volatile("mma.sync.aligned.m16n8k8.row.col.f32.tf32.tf32.f32 "
        "{%0,%1,%2,%3}, {%4,%5,%6,%7}, {%8,%9}, {%0,%1,%2,%3};"
        : "+f"(d[0]),"+f"(d[1]),"+f"(d[2]),"+f"(d[3])
        : "r"(a[0]),"r"(a[1]),"r"(a[2]),"r"(a[3]), "r"(b[0]),"r"(b[1]));
}

// ---------------- LayerNorm --------------------------------------------------
__global__ void ln_kernel(const float* __restrict__ x, const float* __restrict__ g,
                          const float* __restrict__ bta, float* __restrict__ o){
    int row = blockIdx.x;
    int t = threadIdx.x;
    const float* xr = x + (size_t)row * DIM;
    float v[4];
    float s = 0.f;
#pragma unroll
    for (int i=0;i<4;i++){ v[i] = xr[t + 128*i]; s += v[i]; }
    __shared__ float sh[32];
    for (int off=16;off>0;off>>=1) s += __shfl_down_sync(0xffffffffu, s, off);
    if ((t&31)==0) sh[t>>5] = s;
    __syncthreads();
    if (t < 32){
        float r = (t < 4) ? sh[t] : 0.f;
        for (int off=2;off>0;off>>=1) r += __shfl_down_sync(0xffffffffu, r, off);
        if (t==0) sh[0] = r;
    }
    __syncthreads();
    float mean = sh[0] * (1.0f/DIM);
    __syncthreads();
    float sq = 0.f;
#pragma unroll
    for (int i=0;i<4;i++){ v[i] -= mean; sq += v[i]*v[i]; }
    for (int off=16;off>0;off>>=1) sq += __shfl_down_sync(0xffffffffu, sq, off);
    if ((t&31)==0) sh[t>>5] = sq;
    __syncthreads();
    if (t < 32){
        float r = (t < 4) ? sh[t] : 0.f;
        for (int off=2;off>0;off>>=1) r += __shfl_down_sync(0xffffffffu, r, off);
        if (t==0) sh[0] = r;
    }
    __syncthreads();
    float rstd = rsqrtf(sh[0]*(1.0f/DIM) + EPS);
    float* orow = o + (size_t)row*DIM;
#pragma unroll
    for (int i=0;i<4;i++){
        int c = t + 128*i;
        orow[c] = v[i]*rstd*g[c] + bta[c];
    }
}

// ---------------- tf32 tensor-core GEMM, fused epilogue ---------------------
// C[M,N] = A[M,K] @ B  (B is [K,N] row-major, or [N,K] row-major if BT)
// FLAGS: 1 = +bias[col], 2 = gelu, 4 = +residual R (ldc layout), 8 = *ATT_SCALE
// Smem holds operands pre-permuted into mma fragment order so fragment loads
// are a single LDS.128 (A) / LDS.64 (B) per tile.
template<int BM,int BN,int BK,int WM,int WN,int FLAGS,bool BT>
__global__ void __launch_bounds__((BM/WM)*(BN/WN)*32, 2)
gemm_tc(const float* __restrict__ A, const float* __restrict__ B,
        const float* __restrict__ bias, const float* __restrict__ R,
        float* __restrict__ C,
        int M, int N, int K, int lda, int ldb, int ldc,
        long sAb, long sAh, long sBb, long sBh, long sCb, long sCh, int H)
{
    constexpr int WARPS_M = BM/WM, WARPS_N = BN/WN;
    constexpr int THREADS = WARPS_M*WARPS_N*32;
    constexpr int KSTEPS = BK/8;
    constexpr int MT = WM/16, NT = WN/8;
    constexpr int AMT = BM/16;   // 16-row m-tiles per block
    constexpr int BNT = BN/8;    // 8-col n-tiles per block

    __shared__ __align__(16) uint32_t As[KSTEPS*AMT*512];
    __shared__ __align__(16) uint32_t Bs[KSTEPS*BNT*64];

    int z = blockIdx.z;
    int zb = z / H, zh = z % H;
    A += (size_t)zb*sAb + (size_t)zh*sAh;
    B += (size_t)zb*sBb + (size_t)zh*sBh;
    C += (size_t)zb*sCb + (size_t)zh*sCh;

    int t = threadIdx.x;
    int warp = t >> 5, lane = t & 31;
    int wr = warp % WARPS_M, wc = warp / WARPS_M;
    int row0 = blockIdx.y * BM;
    int col0 = blockIdx.x * BN;

    float acc[MT][NT][4];
#pragma unroll
    for (int i=0;i<MT;i++)
#pragma unroll
        for (int j=0;j<NT;j++)
#pragma unroll
            for (int q=0;q<4;q++) acc[i][j][q]=0.f;

    for (int k0=0;k0<K;k0+=BK){
        // ---- A tile -> fragment-order smem ----
#pragma unroll
        for (int i = t; i < BM*BK/4; i += THREADS){
            int m  = i / (BK/4);
            int kc = (i % (BK/4))*4;
            float4 v = *(const float4*)(A + (size_t)(row0+m)*lda + k0 + kc);
            int ks  = kc/8;
            int khi = (kc&7)>>2;           // 0 or 1 (k group within kstep)
            int mt  = m>>4, mm = m&15;
            uint32_t base = (uint32_t)(ks*AMT+mt)*512 + (mm&7)*16 + (khi*2 + (mm>>3));
            As[base + 0]  = f2tf32(v.x);
            As[base + 4]  = f2tf32(v.y);
            As[base + 8]  = f2tf32(v.z);
            As[base + 12] = f2tf32(v.w);
        }
        // ---- B tile -> fragment-order smem ----
        if (!BT){
#pragma unroll
            for (int i = t; i < BK*BN/4; i += THREADS){
                int k  = i / (BN/4);
                int nc = (i % (BN/4))*4;
                float4 v = *(const float4*)(B + (size_t)(k0+k)*ldb + col0 + nc);
                int ks = k/8, kk = k&7;
                uint32_t base = (uint32_t)(ks*BNT + (nc>>3))*64 + ((nc&7)*4 + (kk&3))*2 + (kk>>2);
                Bs[base + 0]  = f2tf32(v.x);
                Bs[base + 8]  = f2tf32(v.y);
                Bs[base + 16] = f2tf32(v.z);
                Bs[base + 24] = f2tf32(v.w);
            }
        } else {
            // B element (k,n) lives at Bglobal[n*ldb + k]
#pragma unroll
            for (int i = t; i < BK*BN/4; i += THREADS){
                int n  = i / (BK/4);
                int kc = (i % (BK/4))*4;
                float4 v = *(const float4*)(B + (size_t)(col0+n)*ldb + k0 + kc);
                int ks  = kc/8;
                int khi = (kc&7)>>2;
                uint32_t base = (uint32_t)(ks*BNT + (n>>3))*64 + (n&7)*8 + khi;
                Bs[base + 0] = f2tf32(v.x);
                Bs[base + 2] = f2tf32(v.y);
                Bs[base + 4] = f2tf32(v.z);
                Bs[base + 6] = f2tf32(v.w);
            }
        }
        __syncthreads();
#pragma unroll
        for (int ks=0; ks<KSTEPS; ks++){
            uint32_t afr[MT][4];
            uint32_t bfr[NT][2];
#pragma unroll
            for (int mt=0; mt<MT; mt++)
                *(uint4*)afr[mt] = *(const uint4*)&As[(uint32_t)(ks*AMT + wr*MT + mt)*512 + lane*4];
#pragma unroll
            for (int nt=0; nt<NT; nt++)
                *(uint2*)bfr[nt] = *(const uint2*)&Bs[(uint32_t)(ks*BNT + wc*NT + nt)*64 + lane*2];
#pragma unroll
            for (int mt=0; mt<MT; mt++)
#pragma unroll
                for (int nt=0; nt<NT; nt++)
                    mma_tf32(acc[mt][nt], afr[mt], bfr[nt]);
        }
        __syncthreads();
    }

    // ---- epilogue ----
    int rbase = row0 + wr*WM + (lane>>2);
    int cbase = col0 + wc*WN + (lane&3)*2;
#pragma unroll
    for (int mt=0; mt<MT; mt++){
#pragma unroll
        for (int half=0; half<2; half++){
            int r = rbase + mt*16 + half*8;
#pragma unroll
            for (int nt=0; nt<NT; nt++){
                int c = cbase + nt*8;
                float v0 = acc[mt][nt][half*2+0];
                float v1 = acc[mt][nt][half*2+1];
                if (FLAGS & 8){ v0 *= ATT_SCALE; v1 *= ATT_SCALE; }
                if (FLAGS & 1){ v0 += bias[c]; v1 += bias[c+1]; }
                if (FLAGS & 2){ v0 = gelu_f(v0); v1 = gelu_f(v1); }
                if (FLAGS & 4){
                    const float2 rr = *(const float2*)(R + (size_t)r*ldc + c);
                    v0 += rr.x; v1 += rr.y;
                }
                float2 o; o.x = v0; o.y = v1;
                *(float2*)(C + (size_t)r*ldc + c) = o;
            }
        }
    }
}

// ---------------- Row softmax over 1024 -------------------------------------
__global__ void softmax_kernel(float* __restrict__ S){
    size_t row = blockIdx.x;
    float* p = S + row*NSEQ;
    int t = threadIdx.x;
    float v[4];
    float m = -1e30f;
#pragma unroll
    for (int i=0;i<4;i++){ v[i] = p[t + 256*i]; m = fmaxf(m, v[i]); }
    __shared__ float sh[32];
    for (int off=16;off>0;off>>=1) m = fmaxf(m, __shfl_down_sync(0xffffffffu,m,off));
    if ((t&31)==0) sh[t>>5]=m;
    __syncthreads();
    if (t<32){
        float r = (t<8)?sh[t]:-1e30f;
        for (int off=4;off>0;off>>=1) r = fmaxf(r, __shfl_down_sync(0xffffffffu,r,off));
        if (t==0) sh[0]=r;
    }
    __syncthreads();
    m = sh[0];
    __syncthreads();
    float s = 0.f;
#pragma unroll
    for (int i=0;i<4;i++){ v[i] = __expf(v[i]-m); s += v[i]; }
    for (int off=16;off>0;off>>=1) s += __shfl_down_sync(0xffffffffu,s,off);
    if ((t&31)==0) sh[t>>5]=s;
    __syncthreads();
    if (t<32){
        float r = (t<8)?sh[t]:0.f;
        for (int off=4;off>0;off>>=1) r += __shfl_down_sync(0xffffffffu,r,off);
        if (t==0) sh[0]=r;
    }
    __syncthreads();
    float inv = 1.0f / sh[0];
#pragma unroll
    for (int i=0;i<4;i++) p[t + 256*i] = v[i]*inv;
}

// ---------------- SE: avg/max pool over tokens ------------------------------
__global__ void pool_kernel(const float* __restrict__ x){
    int bb = blockIdx.x / (DIM/128);
    int ch = (blockIdx.x % (DIM/128))*128 + threadIdx.x;
    const float* p = x + (size_t)bb*NSEQ*DIM + ch;
    float s = 0.f, m = -1e30f;
    for (int n=0;n<NSEQ;n++){ float v = p[(size_t)n*DIM]; s += v; m = fmaxf(m,v); }
    g_pavg[bb*DIM+ch] = s * (1.0f/NSEQ);
    g_pmax[bb*DIM+ch] = m;
}

// ---------------- SE: shared MLP + sigmoid gate -----------------------------
__global__ void semlp_kernel(const float* __restrict__ w1, const float* __restrict__ b1,
                             const float* __restrict__ w2, const float* __restrict__ b2){
    int bb = blockIdx.x;
    int t = threadIdx.x; // 256
    __shared__ float sa[DIM], sm[DIM], ha[SE_H], hm[SE_H];
    sa[t] = g_pavg[bb*DIM+t]; sa[t+256] = g_pavg[bb*DIM+t+256];
    sm[t] = g_pmax[bb*DIM+t]; sm[t+256] = g_pmax[bb*DIM+t+256];
    __syncthreads();
    if (t < SE_H){
        float s = b1[t];
        for (int c=0;c<DIM;c++) s += sa[c]*w1[c*SE_H+t];
        ha[t] = fmaxf(s, 0.f);
    } else if (t < 2*SE_H){
        int j = t - SE_H;
        float s = b1[j];
        for (int c=0;c<DIM;c++) s += sm[c]*w1[c*SE_H+j];
        hm[j] = fmaxf(s, 0.f);
    }
    __syncthreads();
    for (int c=t;c<DIM;c+=256){
        float s = 2.0f*b2[c];
        for (int j=0;j<SE_H;j++) s += (ha[j]+hm[j])*w2[j*DIM+c];
        g_scale[bb*DIM+c] = 1.0f/(1.0f+expf(-s));
    }
}

__global__ void scale_apply_kernel(float* __restrict__ xn){
    int bi = blockIdx.x;
    int t = threadIdx.x; // 512
    int bb = bi >> 10;
    size_t idx = (size_t)bi*DIM + t;
    xn[idx] *= g_scale[bb*DIM + t];
}

// ---------------- Depthwise 3x3 conv over 32x32 grid + bias + gelu ----------
__global__ void dwconv_kernel(const float* __restrict__ h1, const float* __restrict__ w,
                              const float* __restrict__ bias, float* __restrict__ out){
    __shared__ float wsh[256*9];
    int m0 = blockIdx.y*256;
    for (int q=threadIdx.x; q<256*9; q+=256) wsh[q] = w[(size_t)m0*9 + q];
    __syncthreads();
    int bi = blockIdx.x;            // b*NSEQ + n
    int m  = m0 + threadIdx.x;
    int bb = bi >> 10, n = bi & 1023;
    int y = n >> 5, x = n & 31;
    float wv[9];
#pragma unroll
    for (int q=0;q<9;q++) wv[q] = wsh[threadIdx.x*9+q];
    float acc = 0.f;
#pragma unroll
    for (int ky=0;ky<3;ky++){
        int yy = y + ky - 1;
        if (yy < 0 || yy > 31) continue;
#pragma unroll
        for (int kx=0;kx<3;kx++){
            int xx = x + kx - 1;
            if (xx < 0 || xx > 31) continue;
            acc += h1[((size_t)(bb<<10) + (yy<<5) + xx)*MLPD + m] * wv[ky*3+kx];
        }
    }
    out[(size_t)bi*MLPD + m] = gelu_f(acc + bias[m]);
}

// ---------------- skip-merge every 2 layers: x += res; res = x --------------
__global__ void addres_kernel(){
    size_t i = (size_t)blockIdx.x*256 + threadIdx.x;
    float v = g_x[i] + g_res[i];
    g_x[i] = v; g_res[i] = v;
}

// ---------------- host ------------------------------------------------------
extern "C" void kernel_launch(void* const* d_in, const int* in_sizes, int n_in,
                              void* d_out, int out_size){
    const float* x     = (const float*)d_in[0];
    const float* ln1_g = (const float*)d_in[1];
    const float* ln1_b = (const float*)d_in[2];
    const float* w_qkv = (const float*)d_in[3];
    const float* w_out = (const float*)d_in[4];
    const float* b_out = (const float*)d_in[5];
    const float* ln2_g = (const float*)d_in[6];
    const float* ln2_b = (const float*)d_in[7];
    const float* se_w1 = (const float*)d_in[8];
    const float* se_b1 = (const float*)d_in[9];
    const float* se_w2 = (const float*)d_in[10];
    const float* se_b2 = (const float*)d_in[11];
    const float* w1    = (const float*)d_in[12];
    const float* b1    = (const float*)d_in[13];
    const float* dw_w  = (const float*)d_in[14];
    const float* dw_b  = (const float*)d_in[15];
    const float* w2    = (const float*)d_in[16];
    const float* b2    = (const float*)d_in[17];

    float *px,*pres,*pxn,*pqkv,*pS,*pattn,*ph1,*ph2;
    cudaGetSymbolAddress((void**)&px,   g_x);
    cudaGetSymbolAddress((void**)&pres, g_res);
    cudaGetSymbolAddress((void**)&pxn,  g_xn);
    cudaGetSymbolAddress((void**)&pqkv, g_qkv);
    cudaGetSymbolAddress((void**)&pS,   g_scores);
    cudaGetSymbolAddress((void**)&pattn,g_attn);
    cudaGetSymbolAddress((void**)&ph1,  g_h1);
    cudaGetSymbolAddress((void**)&ph2,  g_h2);

    cudaMemcpyAsync(px,   x, (size_t)ROWS*DIM*sizeof(float), cudaMemcpyDeviceToDevice, 0);
    cudaMemcpyAsync(pres, x, (size_t)ROWS*DIM*sizeof(float), cudaMemcpyDeviceToDevice, 0);

    for (int i=0;i<DEPTH;i++){
        // x -> ln1 -> xn
        ln_kernel<<<ROWS,128>>>(px, ln1_g+i*DIM, ln1_b+i*DIM, pxn);
        // qkv = xn @ w_qkv
        gemm_tc<128,128,16,64,32,0,false><<<dim3(3*DIM/128, ROWS/128, 1), 256>>>(
            pxn, w_qkv+(size_t)i*DIM*3*DIM, nullptr, nullptr, pqkv,
            ROWS, 3*DIM, DIM, DIM, 3*DIM, 3*DIM, 0,0,0,0,0,0, 1);
        // scores = Q @ K^T * scale   (B transposed: K stored [n, k])
        gemm_tc<128,128,16,64,32,8,true><<<dim3(NSEQ/128, NSEQ/128, BB*HEADS), 256>>>(
            pqkv, pqkv + DIM, nullptr, nullptr, pS,
            NSEQ, NSEQ, HD, 3*DIM, 3*DIM, NSEQ,
            (long)NSEQ*3*DIM, (long)HD,
            (long)NSEQ*3*DIM, (long)HD,
            (long)HEADS*NSEQ*NSEQ, (long)NSEQ*NSEQ, HEADS);
        softmax_kernel<<<BB*HEADS*NSEQ, 256>>>(pS);
        // attn = P @ V  (merged-head output layout)
        gemm_tc<128,64,16,32,32,0,false><<<dim3(1, NSEQ/128, BB*HEADS), 256>>>(
            pS, pqkv + 2*DIM, nullptr, nullptr, pattn,
            NSEQ, HD, NSEQ, NSEQ, 3*DIM, DIM,
            (long)HEADS*NSEQ*NSEQ, (long)NSEQ*NSEQ,
            (long)NSEQ*3*DIM, (long)HD,
            (long)NSEQ*DIM, (long)HD, HEADS);
        // x = attn @ w_out + b_out + x
        gemm_tc<128,128,16,64,32,5,false><<<dim3(DIM/128, ROWS/128, 1), 256>>>(
            pattn, w_out+(size_t)i*DIM*DIM, b_out+i*DIM, px, px,
            ROWS, DIM, DIM, DIM, DIM, DIM, 0,0,0,0,0,0, 1);
        // x -> ln2 -> xn
        ln_kernel<<<ROWS,128>>>(px, ln2_g+i*DIM, ln2_b+i*DIM, pxn);
        // SE gate
        pool_kernel<<<BB*(DIM/128),128>>>(pxn);
        semlp_kernel<<<BB,256>>>(se_w1+(size_t)i*DIM*SE_H, se_b1+i*SE_H,
                                 se_w2+(size_t)i*SE_H*DIM, se_b2+i*DIM);
        scale_apply_kernel<<<ROWS,512>>>(pxn);
        // h1 = gelu(xn @ w1 + b1)
        gemm_tc<128,128,16,64,32,3,false><<<dim3(MLPD/128, ROWS/128, 1),256>>>(
            pxn, w1+(size_t)i*DIM*MLPD, b1+i*MLPD, nullptr, ph1,
            ROWS, MLPD, DIM, DIM, MLPD, MLPD, 0,0,0,0,0,0, 1);
        // h2 = gelu(dwconv3x3(h1) + dw_b)
        dwconv_kernel<<<dim3(ROWS, MLPD/256), 256>>>(ph1, dw_w+(size_t)i*MLPD*9, dw_b+i*MLPD, ph2);
        // x = gelu(h2 @ w2 + b2) + x
        gemm_tc<128,128,16,64,32,7,false><<<dim3(DIM/128, ROWS/128, 1),256>>>(
            ph2, w2+(size_t)i*MLPD*DIM, b2+i*DIM, px, px,
            ROWS, DIM, MLPD, MLPD, DIM, DIM, 0,0,0,0,0,0, 1);
        // skip merge every 2 layers
        if ((i&1)==1) addres_kernel<<<ROWS*DIM/256, 256>>>();
    }
    cudaMemcpyAsync(d_out, px, (size_t)ROWS*DIM*sizeof(float), cudaMemcpyDeviceToDevice, 0);
}

// round 5
// speedup vs baseline: 4.2058x; 3.3273x over previous
#include <cuda_runtime.h>
#include <cuda_bf16.h>
#include <math.h>
#include <stdint.h>

#define DEPTH 4
#define DIM 512
#define HEADS 8
#define HD 64
#define MLPD 2048
#define SE_H 32
#define BB 8
#define NSEQ 1024
#define ROWS (BB*NSEQ)
#define EPS 1e-5f
#define ATT_SCALE 0.04419417382415922f  /* 512^-0.5 */

typedef __nv_bfloat16 bf16;
typedef __nv_bfloat162 bf162;

// ---------------- scratch (static device memory, no allocs) ----------------
__device__ float g_x[ROWS*DIM];
__device__ float g_res[ROWS*DIM];
__device__ float g_pavg[BB*DIM];
__device__ float g_pmax[BB*DIM];
__device__ float g_scale[BB*DIM];

__device__ bf16 g_xn_bf[ROWS*DIM];
__device__ bf16 g_qkv_bf[ROWS*3*DIM];
__device__ bf16 g_S_bf[(size_t)BB*HEADS*NSEQ*NSEQ];   // 134 MB
__device__ bf16 g_attn_bf[ROWS*DIM];
__device__ bf16 g_h1_bf[ROWS*MLPD];
__device__ bf16 g_h2_bf[ROWS*MLPD];

__device__ bf16 g_wqkv_bf[DEPTH*DIM*3*DIM];
__device__ bf16 g_wout_bf[DEPTH*DIM*DIM];
__device__ bf16 g_w1_bf[DEPTH*DIM*MLPD];
__device__ bf16 g_w2_bf[DEPTH*MLPD*DIM];

__device__ __forceinline__ float gelu_f(float v){
    return 0.5f * v * (1.0f + erff(v * 0.7071067811865476f));
}
__device__ __forceinline__ uint32_t smem_u32(const void* p){
    return (uint32_t)__cvta_generic_to_shared(p);
}
__device__ __forceinline__ void mma_bf16(float* d, const uint32_t* a, const uint32_t* b){
    asm volatile("mma.sync.aligned.m16n8k16.row.col.f32.bf16.bf16.f32 "
        "{%0,%1,%2,%3}, {%4,%5,%6,%7}, {%8,%9}, {%0,%1,%2,%3};"
        : "+f"(d[0]),"+f"(d[1]),"+f"(d[2]),"+f"(d[3])
        : "r"(a[0]),"r"(a[1]),"r"(a[2]),"r"(a[3]), "r"(b[0]),"r"(b[1]));
}
#define LDSM4(r0,r1,r2,r3,addr) \
    asm volatile("ldmatrix.sync.aligned.m8n8.x4.shared.b16 {%0,%1,%2,%3}, [%4];" \
        : "=r"(r0),"=r"(r1),"=r"(r2),"=r"(r3) : "r"(addr))
#define LDSM4T(r0,r1,r2,r3,addr) \
    asm volatile("ldmatrix.sync.aligned.m8n8.x4.trans.shared.b16 {%0,%1,%2,%3}, [%4];" \
        : "=r"(r0),"=r"(r1),"=r"(r2),"=r"(r3) : "r"(addr))
#define CP16(dst,src) \
    asm volatile("cp.async.cg.shared.global [%0], [%1], 16;" :: "r"(dst), "l"(src))
#define CP_COMMIT() asm volatile("cp.async.commit_group;")

// ---------------- fp32 -> bf16 weight convert -------------------------------
__global__ void f2bf_kernel(const float* __restrict__ in, bf16* __restrict__ out, int n){
    int i = blockIdx.x*256 + threadIdx.x;
    if (i < n) out[i] = __float2bfloat16_rn(in[i]);
}

// ---------------- LayerNorm (fp32 in -> bf16 out) ---------------------------
__global__ void ln_kernel(const float* __restrict__ x, const float* __restrict__ g,
                          const float* __restrict__ bta, bf16* __restrict__ o){
    int row = blockIdx.x;
    int t = threadIdx.x;
    const float* xr = x + (size_t)row * DIM;
    float v[4];
    float s = 0.f;
#pragma unroll
    for (int i=0;i<4;i++){ v[i] = xr[t + 128*i]; s += v[i]; }
    __shared__ float sh[32];
    for (int off=16;off>0;off>>=1) s += __shfl_down_sync(0xffffffffu, s, off);
    if ((t&31)==0) sh[t>>5] = s;
    __syncthreads();
    if (t < 32){
        float r = (t < 4) ? sh[t] : 0.f;
        for (int off=2;off>0;off>>=1) r += __shfl_down_sync(0xffffffffu, r, off);
        if (t==0) sh[0] = r;
    }
    __syncthreads();
    float mean = sh[0] * (1.0f/DIM);
    __syncthreads();
    float sq = 0.f;
#pragma unroll
    for (int i=0;i<4;i++){ v[i] -= mean; sq += v[i]*v[i]; }
    for (int off=16;off>0;off>>=1) sq += __shfl_down_sync(0xffffffffu, sq, off);
    if ((t&31)==0) sh[t>>5] = sq;
    __syncthreads();
    if (t < 32){
        float r = (t < 4) ? sh[t] : 0.f;
        for (int off=2;off>0;off>>=1) r += __shfl_down_sync(0xffffffffu, r, off);
        if (t==0) sh[0] = r;
    }
    __syncthreads();
    float rstd = rsqrtf(sh[0]*(1.0f/DIM) + EPS);
    bf16* orow = o + (size_t)row*DIM;
#pragma unroll
    for (int i=0;i<4;i++){
        int c = t + 128*i;
        orow[c] = __float2bfloat16_rn(v[i]*rstd*g[c] + bta[c]);
    }
}

// ---------------- bf16 tensor-core GEMM: cp.async + ldmatrix + m16n8k16 -----
// C = A @ B; A row-major [M,K]; B: [K,N] row-major (NN) or [N,K] row-major (BT)
// FLAGS: 1=+bias, 2=gelu, 4=+residual R(fp32,ldc), 8=*ATT_SCALE. CBF: C bf16.
template<int BM,int BN,int WARPS_M,int WARPS_N,int FLAGS,bool BT,bool CBF>
__global__ void __launch_bounds__(WARPS_M*WARPS_N*32)
gemm_bf16(const bf16* __restrict__ A, const bf16* __restrict__ B,
          const float* __restrict__ bias, const float* __restrict__ R, void* Cv,
          int M, int N, int K, int lda, int ldb, int ldc,
          long sAb, long sAh, long sBb, long sBh, long sCb, long sCh, int H)
{
    constexpr int THREADS = WARPS_M*WARPS_N*32;
    constexpr int WM = BM/WARPS_M, WN = BN/WARPS_N;
    constexpr int MT = WM/16, NT = WN/8;
    constexpr int CH_B = BN/8;     // 16B chunks per B row (NN layout)

    __shared__ __align__(16) bf16 As[2][BM*32];
    __shared__ __align__(16) bf16 Bs[2][32*BN];

    int z = blockIdx.z;
    int zb = z / H, zh = z % H;
    A += (size_t)zb*sAb + (size_t)zh*sAh;
    B += (size_t)zb*sBb + (size_t)zh*sBh;

    int t = threadIdx.x;
    int warp = t >> 5, lane = t & 31;
    int wr = warp % WARPS_M, wc = warp / WARPS_M;
    int row0 = blockIdx.y * BM;
    int col0 = blockIdx.x * BN;

    float acc[MT][NT][4];
#pragma unroll
    for (int i=0;i<MT;i++)
#pragma unroll
        for (int j=0;j<NT;j++)
#pragma unroll
            for (int q=0;q<4;q++) acc[i][j][q]=0.f;

    // ---- async tile loaders (16B chunks, XOR swizzle) ----
    auto loadA = [&](int s, int k0){
#pragma unroll
        for (int i = t; i < BM*4; i += THREADS){
            int r = i >> 2, c = i & 3;
            const bf16* src = A + (size_t)(row0+r)*lda + k0 + c*8;
            uint32_t dst = smem_u32(&As[s][r*32 + ((c ^ ((r>>1)&3))<<3)]);
            CP16(dst, src);
        }
    };
    auto loadB = [&](int s, int k0){
        if (!BT){
#pragma unroll
            for (int i = t; i < 32*CH_B; i += THREADS){
                int r = i / CH_B, c = i % CH_B;
                const bf16* src = B + (size_t)(k0+r)*ldb + col0 + c*8;
                uint32_t dst = smem_u32(&Bs[s][r*BN + ((c ^ (r&7))<<3)]);
                CP16(dst, src);
            }
        } else {
#pragma unroll
            for (int i = t; i < BN*4; i += THREADS){
                int n = i >> 2, c = i & 3;
                const bf16* src = B + (size_t)(col0+n)*ldb + k0 + c*8;
                uint32_t dst = smem_u32(&Bs[s][n*32 + ((c ^ ((n>>1)&3))<<3)]);
                CP16(dst, src);
            }
        }
    };

    loadA(0, 0); loadB(0, 0); CP_COMMIT();

    int s = 0;
    for (int k0 = 0; k0 < K; k0 += 32){
        bool next = (k0 + 32 < K);
        if (next){ loadA(s^1, k0+32); loadB(s^1, k0+32); CP_COMMIT(); }
        if (next) asm volatile("cp.async.wait_group 1;");
        else      asm volatile("cp.async.wait_group 0;");
        __syncthreads();

#pragma unroll
        for (int kp = 0; kp < 2; kp++){
            uint32_t afr[MT][4];
#pragma unroll
            for (int mt = 0; mt < MT; mt++){
                int row = wr*WM + mt*16 + (lane & 15);
                int chunk = kp*2 + (lane >> 4);
                uint32_t addr = smem_u32(&As[s][row*32 + ((chunk ^ ((row>>1)&3))<<3)]);
                LDSM4(afr[mt][0], afr[mt][1], afr[mt][2], afr[mt][3], addr);
            }
            uint32_t bfr[NT][2];
#pragma unroll
            for (int j = 0; j < NT/2; j++){
                uint32_t r0,r1,r2,r3;
                if (!BT){
                    int krow = kp*16 + (lane&7) + ((lane>>3)&1)*8;
                    int chunk = wc*NT + j*2 + (lane >> 4);
                    uint32_t addr = smem_u32(&Bs[s][krow*BN + ((chunk ^ (krow&7))<<3)]);
                    LDSM4T(r0,r1,r2,r3, addr);
                } else {
                    int nrow = wc*WN + j*16 + ((lane>>4)<<3) + (lane&7);
                    int chunk = kp*2 + ((lane>>3)&1);
                    uint32_t addr = smem_u32(&Bs[s][nrow*32 + ((chunk ^ ((nrow>>1)&3))<<3)]);
                    LDSM4(r0,r1,r2,r3, addr);
                }
                bfr[2*j][0]=r0; bfr[2*j][1]=r1; bfr[2*j+1][0]=r2; bfr[2*j+1][1]=r3;
            }
#pragma unroll
            for (int mt = 0; mt < MT; mt++)
#pragma unroll
                for (int nt = 0; nt < NT; nt++)
                    mma_bf16(acc[mt][nt], afr[mt], bfr[nt]);
        }
        __syncthreads();
        s ^= 1;
    }

    // ---- epilogue ----
    int rbase = row0 + wr*WM + (lane>>2);
    int cbase = col0 + wc*WN + (lane&3)*2;
#pragma unroll
    for (int mt=0; mt<MT; mt++){
#pragma unroll
        for (int half=0; half<2; half++){
            int r = rbase + mt*16 + half*8;
#pragma unroll
            for (int nt=0; nt<NT; nt++){
                int c = cbase + nt*8;
                float v0 = acc[mt][nt][half*2+0];
                float v1 = acc[mt][nt][half*2+1];
                if (FLAGS & 8){ v0 *= ATT_SCALE; v1 *= ATT_SCALE; }
                if (FLAGS & 1){ v0 += bias[c]; v1 += bias[c+1]; }
                if (FLAGS & 2){ v0 = gelu_f(v0); v1 = gelu_f(v1); }
                if (FLAGS & 4){
                    const float2 rr = *(const float2*)(R + (size_t)r*ldc + c);
                    v0 += rr.x; v1 += rr.y;
                }
                if (CBF){
                    bf16* C = (bf16*)Cv + (size_t)zb*sCb + (size_t)zh*sCh;
                    *(bf162*)(C + (size_t)r*ldc + c) = __floats2bfloat162_rn(v0, v1);
                } else {
                    float* C = (float*)Cv + (size_t)zb*sCb + (size_t)zh*sCh;
                    float2 o; o.x = v0; o.y = v1;
                    *(float2*)(C + (size_t)r*ldc + c) = o;
                }
            }
        }
    }
}

// ---------------- Row softmax over 1024, bf16 in/out -------------------------
__global__ void softmax_bf_kernel(bf16* __restrict__ S){
    size_t row = blockIdx.x;
    bf16* p = S + row*NSEQ;
    int t = threadIdx.x;
    uint2 u = ((const uint2*)p)[t];           // 4 bf16
    bf162 h0 = *(bf162*)&u.x;
    bf162 h1 = *(bf162*)&u.y;
    float2 f0 = __bfloat1622float2(h0);
    float2 f1 = __bfloat1622float2(h1);
    float v[4] = {f0.x, f0.y, f1.x, f1.y};
    float m = fmaxf(fmaxf(v[0],v[1]), fmaxf(v[2],v[3]));
    __shared__ float sh[32];
    for (int off=16;off>0;off>>=1) m = fmaxf(m, __shfl_down_sync(0xffffffffu,m,off));
    if ((t&31)==0) sh[t>>5]=m;
    __syncthreads();
    if (t<32){
        float r = (t<8)?sh[t]:-1e30f;
        for (int off=4;off>0;off>>=1) r = fmaxf(r, __shfl_down_sync(0xffffffffu,r,off));
        if (t==0) sh[0]=r;
    }
    __syncthreads();
    m = sh[0];
    __syncthreads();
    float s = 0.f;
#pragma unroll
    for (int i=0;i<4;i++){ v[i] = __expf(v[i]-m); s += v[i]; }
    for (int off=16;off>0;off>>=1) s += __shfl_down_sync(0xffffffffu,s,off);
    if ((t&31)==0) sh[t>>5]=s;
    __syncthreads();
    if (t<32){
        float r = (t<8)?sh[t]:0.f;
        for (int off=4;off>0;off>>=1) r += __shfl_down_sync(0xffffffffu,r,off);
        if (t==0) sh[0]=r;
    }
    __syncthreads();
    float inv = 1.0f / sh[0];
    uint2 o;
    *(bf162*)&o.x = __floats2bfloat162_rn(v[0]*inv, v[1]*inv);
    *(bf162*)&o.y = __floats2bfloat162_rn(v[2]*inv, v[3]*inv);
    ((uint2*)p)[t] = o;
}

// ---------------- SE: avg/max pool over tokens (bf16 in) ---------------------
__global__ void pool_kernel(const bf16* __restrict__ x){
    int bb = blockIdx.x / (DIM/128);
    int ch = (blockIdx.x % (DIM/128))*128 + threadIdx.x;
    const bf16* p = x + (size_t)bb*NSEQ*DIM + ch;
    float s = 0.f, m = -1e30f;
    for (int n=0;n<NSEQ;n++){ float v = __bfloat162float(p[(size_t)n*DIM]); s += v; m = fmaxf(m,v); }
    g_pavg[bb*DIM+ch] = s * (1.0f/NSEQ);
    g_pmax[bb*DIM+ch] = m;
}

// ---------------- SE: shared MLP + sigmoid gate ------------------------------
__global__ void semlp_kernel(const float* __restrict__ w1, const float* __restrict__ b1,
                             const float* __restrict__ w2, const float* __restrict__ b2){
    int bb = blockIdx.x;
    int t = threadIdx.x; // 256
    __shared__ float sa[DIM], sm[DIM], ha[SE_H], hm[SE_H];
    sa[t] = g_pavg[bb*DIM+t]; sa[t+256] = g_pavg[bb*DIM+t+256];
    sm[t] = g_pmax[bb*DIM+t]; sm[t+256] = g_pmax[bb*DIM+t+256];
    __syncthreads();
    if (t < SE_H){
        float s = b1[t];
        for (int c=0;c<DIM;c++) s += sa[c]*w1[c*SE_H+t];
        ha[t] = fmaxf(s, 0.f);
    } else if (t < 2*SE_H){
        int j = t - SE_H;
        float s = b1[j];
        for (int c=0;c<DIM;c++) s += sm[c]*w1[c*SE_H+j];
        hm[j] = fmaxf(s, 0.f);
    }
    __syncthreads();
    for (int c=t;c<DIM;c+=256){
        float s = 2.0f*b2[c];
        for (int j=0;j<SE_H;j++) s += (ha[j]+hm[j])*w2[j*DIM+c];
        g_scale[bb*DIM+c] = 1.0f/(1.0f+expf(-s));
    }
}

__global__ void scale_apply_kernel(bf16* __restrict__ xn){
    int bi = blockIdx.x;
    int t = threadIdx.x; // 512
    int bb = bi >> 10;
    size_t idx = (size_t)bi*DIM + t;
    xn[idx] = __float2bfloat16_rn(__bfloat162float(xn[idx]) * g_scale[bb*DIM + t]);
}

// ---------------- Depthwise 3x3 conv + bias + gelu (bf16 in/out) -------------
__global__ void dwconv_kernel(const bf16* __restrict__ h1, const float* __restrict__ w,
                              const float* __restrict__ bias, bf16* __restrict__ out){
    __shared__ float wsh[256*9];
    int m0 = blockIdx.y*256;
    for (int q=threadIdx.x; q<256*9; q+=256) wsh[q] = w[(size_t)m0*9 + q];
    __syncthreads();
    int bi = blockIdx.x;            // b*NSEQ + n
    int m  = m0 + threadIdx.x;
    int bb = bi >> 10, n = bi & 1023;
    int y = n >> 5, x = n & 31;
    float wv[9];
#pragma unroll
    for (int q=0;q<9;q++) wv[q] = wsh[threadIdx.x*9+q];
    float acc = 0.f;
#pragma unroll
    for (int ky=0;ky<3;ky++){
        int yy = y + ky - 1;
        if (yy < 0 || yy > 31) continue;
#pragma unroll
        for (int kx=0;kx<3;kx++){
            int xx = x + kx - 1;
            if (xx < 0 || xx > 31) continue;
            acc += __bfloat162float(h1[((size_t)(bb<<10) + (yy<<5) + xx)*MLPD + m]) * wv[ky*3+kx];
        }
    }
    out[(size_t)bi*MLPD + m] = __float2bfloat16_rn(gelu_f(acc + bias[m]));
}

// ---------------- skip-merge every 2 layers ----------------------------------
__global__ void addres_kernel(){
    size_t i = (size_t)blockIdx.x*256 + threadIdx.x;
    float v = g_x[i] + g_res[i];
    g_x[i] = v; g_res[i] = v;
}

// ---------------- host -------------------------------------------------------
extern "C" void kernel_launch(void* const* d_in, const int* in_sizes, int n_in,
                              void* d_out, int out_size){
    const float* x     = (const float*)d_in[0];
    const float* ln1_g = (const float*)d_in[1];
    const float* ln1_b = (const float*)d_in[2];
    const float* w_qkv = (const float*)d_in[3];
    const float* w_out = (const float*)d_in[4];
    const float* b_out = (const float*)d_in[5];
    const float* ln2_g = (const float*)d_in[6];
    const float* ln2_b = (const float*)d_in[7];
    const float* se_w1 = (const float*)d_in[8];
    const float* se_b1 = (const float*)d_in[9];
    const float* se_w2 = (const float*)d_in[10];
    const float* se_b2 = (const float*)d_in[11];
    const float* w1    = (const float*)d_in[12];
    const float* b1    = (const float*)d_in[13];
    const float* dw_w  = (const float*)d_in[14];
    const float* dw_b  = (const float*)d_in[15];
    const float* w2    = (const float*)d_in[16];
    const float* b2    = (const float*)d_in[17];

    float *px, *pres;
    bf16 *pxn, *pqkv, *pS, *pattn, *ph1, *ph2, *pwqkv, *pwout, *pw1, *pw2;
    cudaGetSymbolAddress((void**)&px,    g_x);
    cudaGetSymbolAddress((void**)&pres,  g_res);
    cudaGetSymbolAddress((void**)&pxn,   g_xn_bf);
    cudaGetSymbolAddress((void**)&pqkv,  g_qkv_bf);
    cudaGetSymbolAddress((void**)&pS,    g_S_bf);
    cudaGetSymbolAddress((void**)&pattn, g_attn_bf);
    cudaGetSymbolAddress((void**)&ph1,   g_h1_bf);
    cudaGetSymbolAddress((void**)&ph2,   g_h2_bf);
    cudaGetSymbolAddress((void**)&pwqkv, g_wqkv_bf);
    cudaGetSymbolAddress((void**)&pwout, g_wout_bf);
    cudaGetSymbolAddress((void**)&pw1,   g_w1_bf);
    cudaGetSymbolAddress((void**)&pw2,   g_w2_bf);

    cudaMemcpyAsync(px,   x, (size_t)ROWS*DIM*sizeof(float), cudaMemcpyDeviceToDevice, 0);
    cudaMemcpyAsync(pres, x, (size_t)ROWS*DIM*sizeof(float), cudaMemcpyDeviceToDevice, 0);

    // convert weights to bf16 (per launch; deterministic)
    {
        int n;
        n = DEPTH*DIM*3*DIM; f2bf_kernel<<<(n+255)/256,256>>>(w_qkv, pwqkv, n);
        n = DEPTH*DIM*DIM;   f2bf_kernel<<<(n+255)/256,256>>>(w_out, pwout, n);
        n = DEPTH*DIM*MLPD;  f2bf_kernel<<<(n+255)/256,256>>>(w1,    pw1,   n);
        n = DEPTH*MLPD*DIM;  f2bf_kernel<<<(n+255)/256,256>>>(w2,    pw2,   n);
    }

    for (int i=0;i<DEPTH;i++){
        // x -> ln1 -> xn (bf16)
        ln_kernel<<<ROWS,128>>>(px, ln1_g+i*DIM, ln1_b+i*DIM, pxn);
        // qkv = xn @ w_qkv  (bf16 out)
        gemm_bf16<128,128,2,4,0,false,true><<<dim3(3*DIM/128, ROWS/128, 1), 256>>>(
            pxn, pwqkv+(size_t)i*DIM*3*DIM, nullptr, nullptr, pqkv,
            ROWS, 3*DIM, DIM, DIM, 3*DIM, 3*DIM, 0,0,0,0,0,0, 1);
        // scores = Q @ K^T * scale (BT, bf16 out)
        gemm_bf16<128,128,2,4,8,true,true><<<dim3(NSEQ/128, NSEQ/128, BB*HEADS), 256>>>(
            pqkv, pqkv + DIM, nullptr, nullptr, pS,
            NSEQ, NSEQ, HD, 3*DIM, 3*DIM, NSEQ,
            (long)NSEQ*3*DIM, (long)HD,
            (long)NSEQ*3*DIM, (long)HD,
            (long)HEADS*NSEQ*NSEQ, (long)NSEQ*NSEQ, HEADS);
        softmax_bf_kernel<<<BB*HEADS*NSEQ, 256>>>(pS);
        // attn = P @ V  (bf16 out, merged-head layout)
        gemm_bf16<128,64,4,2,0,false,true><<<dim3(1, NSEQ/128, BB*HEADS), 256>>>(
            pS, pqkv + 2*DIM, nullptr, nullptr, pattn,
            NSEQ, HD, NSEQ, NSEQ, 3*DIM, DIM,
            (long)HEADS*NSEQ*NSEQ, (long)NSEQ*NSEQ,
            (long)NSEQ*3*DIM, (long)HD,
            (long)NSEQ*DIM, (long)HD, HEADS);
        // x = attn @ w_out + b_out + x  (fp32 out)
        gemm_bf16<128,128,2,4,5,false,false><<<dim3(DIM/128, ROWS/128, 1), 256>>>(
            pattn, pwout+(size_t)i*DIM*DIM, b_out+i*DIM, px, px,
            ROWS, DIM, DIM, DIM, DIM, DIM, 0,0,0,0,0,0, 1);
        // x -> ln2 -> xn (bf16)
        ln_kernel<<<ROWS,128>>>(px, ln2_g+i*DIM, ln2_b+i*DIM, pxn);
        // SE gate
        pool_kernel<<<BB*(DIM/128),128>>>(pxn);
        semlp_kernel<<<BB,256>>>(se_w1+(size_t)i*DIM*SE_H, se_b1+i*SE_H,
                                 se_w2+(size_t)i*SE_H*DIM, se_b2+i*DIM);
        scale_apply_kernel<<<ROWS,512>>>(pxn);
        // h1 = gelu(xn @ w1 + b1)  (bf16 out)
        gemm_bf16<128,128,2,4,3,false,true><<<dim3(MLPD/128, ROWS/128, 1),256>>>(
            pxn, pw1+(size_t)i*DIM*MLPD, b1+i*MLPD, nullptr, ph1,
            ROWS, MLPD, DIM, DIM, MLPD, MLPD, 0,0,0,0,0,0, 1);
        // h2 = gelu(dwconv3x3(h1) + dw_b)
        dwconv_kernel<<<dim3(ROWS, MLPD/256), 256>>>(ph1, dw_w+(size_t)i*MLPD*9, dw_b+i*MLPD, ph2);
        // x = gelu(h2 @ w2 + b2) + x  (fp32 out)
        gemm_bf16<128,128,2,4,7,false,false><<<dim3(DIM/128, ROWS/128, 1),256>>>(
            ph2, pw2+(size_t)i*MLPD*DIM, b2+i*DIM, px, px,
            ROWS, DIM, MLPD, MLPD, DIM, DIM, 0,0,0,0,0,0, 1);
        // skip merge every 2 layers
        if ((i&1)==1) addres_kernel<<<ROWS*DIM/256, 256>>>();
    }
    cudaMemcpyAsync(d_out, px, (size_t)ROWS*DIM*sizeof(float), cudaMemcpyDeviceToDevice, 0);
}

// round 8
// speedup vs baseline: 5.1756x; 1.2306x over previous
#include <cuda_runtime.h>
#include <cuda_bf16.h>
#include <math.h>
#include <stdint.h>

#define DEPTH 4
#define DIM 512
#define HEADS 8
#define HD 64
#define MLPD 2048
#define SE_H 32
#define BB 8
#define NSEQ 1024
#define ROWS (BB*NSEQ)
#define EPS 1e-5f
#define ATT_SCALE 0.04419417382415922f  /* 512^-0.5 */

typedef __nv_bfloat16 bf16;
typedef __nv_bfloat162 bf162;

// ---------------- scratch (static device memory, no allocs) ----------------
__device__ float g_x[ROWS*DIM];
__device__ float g_res[ROWS*DIM];
__device__ float g_pavg[BB*DIM];
__device__ float g_pmax[BB*DIM];
__device__ float g_scale[BB*DIM];

__device__ bf16 g_xn_bf[ROWS*DIM];
__device__ bf16 g_qkv_bf[ROWS*3*DIM];
__device__ bf16 g_attn_bf[ROWS*DIM];
__device__ bf16 g_h1_bf[ROWS*MLPD];
__device__ bf16 g_h2_bf[ROWS*MLPD];

__device__ bf16 g_wqkv_bf[DEPTH*DIM*3*DIM];
__device__ bf16 g_wout_bf[DEPTH*DIM*DIM];
__device__ bf16 g_w1_bf[DEPTH*DIM*MLPD];
__device__ bf16 g_w2_bf[DEPTH*MLPD*DIM];

__device__ __forceinline__ float gelu_f(float v){
    return 0.5f * v * (1.0f + erff(v * 0.7071067811865476f));
}
__device__ __forceinline__ uint32_t smem_u32(const void* p){
    return (uint32_t)__cvta_generic_to_shared(p);
}
__device__ __forceinline__ void mma_bf16(float* d, const uint32_t* a, const uint32_t* b){
    asm volatile("mma.sync.aligned.m16n8k16.row.col.f32.bf16.bf16.f32 "
        "{%0,%1,%2,%3}, {%4,%5,%6,%7}, {%8,%9}, {%0,%1,%2,%3};"
        : "+f"(d[0]),"+f"(d[1]),"+f"(d[2]),"+f"(d[3])
        : "r"(a[0]),"r"(a[1]),"r"(a[2]),"r"(a[3]), "r"(b[0]),"r"(b[1]));
}
#define LDSM4(r0,r1,r2,r3,addr) \
    asm volatile("ldmatrix.sync.aligned.m8n8.x4.shared.b16 {%0,%1,%2,%3}, [%4];" \
        : "=r"(r0),"=r"(r1),"=r"(r2),"=r"(r3) : "r"(addr))
#define LDSM4T(r0,r1,r2,r3,addr) \
    asm volatile("ldmatrix.sync.aligned.m8n8.x4.trans.shared.b16 {%0,%1,%2,%3}, [%4];" \
        : "=r"(r0),"=r"(r1),"=r"(r2),"=r"(r3) : "r"(addr))
#define CP16(dst,src) \
    asm volatile("cp.async.cg.shared.global [%0], [%1], 16;" :: "r"(dst), "l"(src))
#define CP_COMMIT() asm volatile("cp.async.commit_group;")

// ---------------- fp32 -> bf16 weight convert -------------------------------
__global__ void f2bf_kernel(const float* __restrict__ in, bf16* __restrict__ out, int n){
    int i = blockIdx.x*256 + threadIdx.x;
    if (i < n) out[i] = __float2bfloat16_rn(in[i]);
}

// ---------------- LayerNorm (fp32 in -> bf16 out) ---------------------------
__global__ void ln_kernel(const float* __restrict__ x, const float* __restrict__ g,
                          const float* __restrict__ bta, bf16* __restrict__ o){
    int row = blockIdx.x;
    int t = threadIdx.x;
    const float* xr = x + (size_t)row * DIM;
    float v[4];
    float s = 0.f;
#pragma unroll
    for (int i=0;i<4;i++){ v[i] = xr[t + 128*i]; s += v[i]; }
    __shared__ float sh[32];
    for (int off=16;off>0;off>>=1) s += __shfl_down_sync(0xffffffffu, s, off);
    if ((t&31)==0) sh[t>>5] = s;
    __syncthreads();
    if (t < 32){
        float r = (t < 4) ? sh[t] : 0.f;
        for (int off=2;off>0;off>>=1) r += __shfl_down_sync(0xffffffffu, r, off);
        if (t==0) sh[0] = r;
    }
    __syncthreads();
    float mean = sh[0] * (1.0f/DIM);
    __syncthreads();
    float sq = 0.f;
#pragma unroll
    for (int i=0;i<4;i++){ v[i] -= mean; sq += v[i]*v[i]; }
    for (int off=16;off>0;off>>=1) sq += __shfl_down_sync(0xffffffffu, sq, off);
    if ((t&31)==0) sh[t>>5] = sq;
    __syncthreads();
    if (t < 32){
        float r = (t < 4) ? sh[t] : 0.f;
        for (int off=2;off>0;off>>=1) r += __shfl_down_sync(0xffffffffu, r, off);
        if (t==0) sh[0] = r;
    }
    __syncthreads();
    float rstd = rsqrtf(sh[0]*(1.0f/DIM) + EPS);
    bf16* orow = o + (size_t)row*DIM;
#pragma unroll
    for (int i=0;i<4;i++){
        int c = t + 128*i;
        orow[c] = __float2bfloat16_rn(v[i]*rstd*g[c] + bta[c]);
    }
}

// ---------------- Flash attention: fused QK^T + softmax + PV -----------------
// grid (NSEQ/128, BB*HEADS), block 256 (8 warps, each owns 16 Q rows)
__global__ void __launch_bounds__(256)
flash_attn_kernel(const bf16* __restrict__ qkv, bf16* __restrict__ out){
    int bh = blockIdx.y;
    int b = bh >> 3, h = bh & 7;
    int i0 = blockIdx.x * 128;
    const bf16* base = qkv + (size_t)b*NSEQ*3*DIM;
    const bf16* Qp = base + (size_t)h*HD;
    const bf16* Kp = base + DIM + (size_t)h*HD;
    const bf16* Vp = base + 2*DIM + (size_t)h*HD;

    __shared__ __align__(16) bf16 Qs[128*64];
    __shared__ __align__(16) bf16 Ks[2][64*64];
    __shared__ __align__(16) bf16 Vs[2][64*64];

    int t = threadIdx.x, warp = t >> 5, lane = t & 31;

    // Q tile -> smem (swizzled)
#pragma unroll
    for (int i = t; i < 128*8; i += 256){
        int r = i >> 3, c = i & 7;
        CP16(smem_u32(&Qs[r*64 + ((c ^ (r&7))<<3)]), Qp + (size_t)(i0+r)*(3*DIM) + c*8);
    }
    auto loadKV = [&](int s, int j0){
#pragma unroll
        for (int i = t; i < 64*8; i += 256){
            int r = i >> 3, c = i & 7;
            CP16(smem_u32(&Ks[s][r*64 + ((c ^ (r&7))<<3)]), Kp + (size_t)(j0+r)*(3*DIM) + c*8);
        }
#pragma unroll
        for (int i = t; i < 64*8; i += 256){
            int r = i >> 3, c = i & 7;
            CP16(smem_u32(&Vs[s][r*64 + ((c ^ (r&7))<<3)]), Vp + (size_t)(j0+r)*(3*DIM) + c*8);
        }
    };
    loadKV(0, 0);
    CP_COMMIT();
    asm volatile("cp.async.wait_group 0;");
    __syncthreads();

    // Q fragments (held in registers for the whole kernel)
    uint32_t qf[4][4];
#pragma unroll
    for (int kp=0;kp<4;kp++){
        int row = warp*16 + (lane & 15);
        int chunk = kp*2 + (lane >> 4);
        uint32_t addr = smem_u32(&Qs[row*64 + ((chunk ^ (row&7))<<3)]);
        LDSM4(qf[kp][0], qf[kp][1], qf[kp][2], qf[kp][3], addr);
    }

    float of[8][4];
#pragma unroll
    for (int nt=0;nt<8;nt++)
#pragma unroll
        for (int q=0;q<4;q++) of[nt][q] = 0.f;
    float m0 = -1e30f, m1 = -1e30f, l0 = 0.f, l1 = 0.f;

    int s = 0;
    for (int it=0; it<16; it++){
        if (it < 15){ loadKV(s^1, (it+1)*64); CP_COMMIT(); }

        // ---- S = Q @ K^T (this 64-key tile) ----
        float sacc[8][4];
#pragma unroll
        for (int nt=0;nt<8;nt++)
#pragma unroll
            for (int q=0;q<4;q++) sacc[nt][q] = 0.f;
#pragma unroll
        for (int kp=0;kp<4;kp++){
            uint32_t bfr[8][2];
#pragma unroll
            for (int j=0;j<4;j++){
                int nrow = j*16 + ((lane>>4)<<3) + (lane&7);
                int chunk = kp*2 + ((lane>>3)&1);
                uint32_t addr = smem_u32(&Ks[s][nrow*64 + ((chunk ^ (nrow&7))<<3)]);
                uint32_t r0,r1,r2,r3; LDSM4(r0,r1,r2,r3, addr);
                bfr[2*j][0]=r0; bfr[2*j][1]=r1; bfr[2*j+1][0]=r2; bfr[2*j+1][1]=r3;
            }
#pragma unroll
            for (int nt=0;nt<8;nt++) mma_bf16(sacc[nt], qf[kp], bfr[nt]);
        }

        // ---- online softmax (rows r = warp*16 + lane/4 and r+8) ----
        float tm0 = -1e30f, tm1 = -1e30f;
#pragma unroll
        for (int nt=0;nt<8;nt++){
            sacc[nt][0] *= ATT_SCALE; sacc[nt][1] *= ATT_SCALE;
            sacc[nt][2] *= ATT_SCALE; sacc[nt][3] *= ATT_SCALE;
            tm0 = fmaxf(tm0, fmaxf(sacc[nt][0], sacc[nt][1]));
            tm1 = fmaxf(tm1, fmaxf(sacc[nt][2], sacc[nt][3]));
        }
        tm0 = fmaxf(tm0, __shfl_xor_sync(0xffffffffu, tm0, 1));
        tm0 = fmaxf(tm0, __shfl_xor_sync(0xffffffffu, tm0, 2));
        tm1 = fmaxf(tm1, __shfl_xor_sync(0xffffffffu, tm1, 1));
        tm1 = fmaxf(tm1, __shfl_xor_sync(0xffffffffu, tm1, 2));
        float mn0 = fmaxf(m0, tm0), mn1 = fmaxf(m1, tm1);
        float a0 = __expf(m0 - mn0), a1 = __expf(m1 - mn1);
        m0 = mn0; m1 = mn1;
        float rs0 = 0.f, rs1 = 0.f;
#pragma unroll
        for (int nt=0;nt<8;nt++){
            sacc[nt][0] = __expf(sacc[nt][0] - m0);
            sacc[nt][1] = __expf(sacc[nt][1] - m0);
            sacc[nt][2] = __expf(sacc[nt][2] - m1);
            sacc[nt][3] = __expf(sacc[nt][3] - m1);
            rs0 += sacc[nt][0] + sacc[nt][1];
            rs1 += sacc[nt][2] + sacc[nt][3];
        }
        rs0 += __shfl_xor_sync(0xffffffffu, rs0, 1);
        rs0 += __shfl_xor_sync(0xffffffffu, rs0, 2);
        rs1 += __shfl_xor_sync(0xffffffffu, rs1, 1);
        rs1 += __shfl_xor_sync(0xffffffffu, rs1, 2);
        l0 = l0*a0 + rs0;
        l1 = l1*a1 + rs1;
#pragma unroll
        for (int nt=0;nt<8;nt++){
            of[nt][0] *= a0; of[nt][1] *= a0;
            of[nt][2] *= a1; of[nt][3] *= a1;
        }

        // ---- pack P into A-fragments (acc layout == A-frag layout) ----
        uint32_t pf[4][4];
#pragma unroll
        for (int kc=0;kc<4;kc++){
            bf162 p0 = __floats2bfloat162_rn(sacc[2*kc  ][0], sacc[2*kc  ][1]);
            bf162 p1 = __floats2bfloat162_rn(sacc[2*kc  ][2], sacc[2*kc  ][3]);
            bf162 p2 = __floats2bfloat162_rn(sacc[2*kc+1][0], sacc[2*kc+1][1]);
            bf162 p3 = __floats2bfloat162_rn(sacc[2*kc+1][2], sacc[2*kc+1][3]);
            pf[kc][0] = *(uint32_t*)&p0;
            pf[kc][1] = *(uint32_t*)&p1;
            pf[kc][2] = *(uint32_t*)&p2;
            pf[kc][3] = *(uint32_t*)&p3;
        }

        // ---- O += P @ V ----
#pragma unroll
        for (int kp=0;kp<4;kp++){
            uint32_t vfr[8][2];
#pragma unroll
            for (int j=0;j<4;j++){
                int krow = kp*16 + (lane&7) + ((lane>>3)&1)*8;
                int chunk = j*2 + (lane>>4);
                uint32_t addr = smem_u32(&Vs[s][krow*64 + ((chunk ^ (krow&7))<<3)]);
                uint32_t r0,r1,r2,r3; LDSM4T(r0,r1,r2,r3, addr);
                vfr[2*j][0]=r0; vfr[2*j][1]=r1; vfr[2*j+1][0]=r2; vfr[2*j+1][1]=r3;
            }
#pragma unroll
            for (int nt=0;nt<8;nt++) mma_bf16(of[nt], pf[kp], vfr[nt]);
        }

        if (it < 15) asm volatile("cp.async.wait_group 0;");
        __syncthreads();
        s ^= 1;
    }

    // ---- normalize and store (merged-head layout [b*n, DIM]) ----
    float inv0 = 1.0f / l0, inv1 = 1.0f / l1;
    int r = warp*16 + (lane>>2);
    bf16* op = out + ((size_t)(b*NSEQ + i0 + r))*DIM + h*HD + (lane&3)*2;
#pragma unroll
    for (int nt=0;nt<8;nt++){
        bf162 o0 = __floats2bfloat162_rn(of[nt][0]*inv0, of[nt][1]*inv0);
        bf162 o1 = __floats2bfloat162_rn(of[nt][2]*inv1, of[nt][3]*inv1);
        *(bf162*)(op + nt*8)            = o0;
        *(bf162*)(op + 8*DIM + nt*8)    = o1;
    }
}

// ---------------- bf16 tensor-core GEMM: cp.async + ldmatrix + m16n8k16 -----
// C = A @ B; A row-major [M,K]; B: [K,N] row-major (NN) or [N,K] row-major (BT)
// FLAGS: 1=+bias, 2=gelu, 4=+residual R(fp32,ldc), 8=*ATT_SCALE. CBF: C bf16.
template<int BM,int BN,int WARPS_M,int WARPS_N,int FLAGS,bool BT,bool CBF>
__global__ void __launch_bounds__(WARPS_M*WARPS_N*32)
gemm_bf16(const bf16* __restrict__ A, const bf16* __restrict__ B,
          const float* __restrict__ bias, const float* __restrict__ R, void* Cv,
          int M, int N, int K, int lda, int ldb, int ldc,
          long sAb, long sAh, long sBb, long sBh, long sCb, long sCh, int H)
{
    constexpr int THREADS = WARPS_M*WARPS_N*32;
    constexpr int WM = BM/WARPS_M, WN = BN/WARPS_N;
    constexpr int MT = WM/16, NT = WN/8;
    constexpr int CH_B = BN/8;

    __shared__ __align__(16) bf16 As[2][BM*32];
    __shared__ __align__(16) bf16 Bs[2][32*BN];

    int z = blockIdx.z;
    int zb = z / H, zh = z % H;
    A += (size_t)zb*sAb + (size_t)zh*sAh;
    B += (size_t)zb*sBb + (size_t)zh*sBh;

    int t = threadIdx.x;
    int warp = t >> 5, lane = t & 31;
    int wr = warp % WARPS_M, wc = warp / WARPS_M;
    int row0 = blockIdx.y * BM;
    int col0 = blockIdx.x * BN;

    float acc[MT][NT][4];
#pragma unroll
    for (int i=0;i<MT;i++)
#pragma unroll
        for (int j=0;j<NT;j++)
#pragma unroll
            for (int q=0;q<4;q++) acc[i][j][q]=0.f;

    auto loadA = [&](int s, int k0){
#pragma unroll
        for (int i = t; i < BM*4; i += THREADS){
            int r = i >> 2, c = i & 3;
            const bf16* src = A + (size_t)(row0+r)*lda + k0 + c*8;
            uint32_t dst = smem_u32(&As[s][r*32 + ((c ^ ((r>>1)&3))<<3)]);
            CP16(dst, src);
        }
    };
    auto loadB = [&](int s, int k0){
        if (!BT){
#pragma unroll
            for (int i = t; i < 32*CH_B; i += THREADS){
                int r = i / CH_B, c = i % CH_B;
                const bf16* src = B + (size_t)(k0+r)*ldb + col0 + c*8;
                uint32_t dst = smem_u32(&Bs[s][r*BN + ((c ^ (r&7))<<3)]);
                CP16(dst, src);
            }
        } else {
#pragma unroll
            for (int i = t; i < BN*4; i += THREADS){
                int n = i >> 2, c = i & 3;
                const bf16* src = B + (size_t)(col0+n)*ldb + k0 + c*8;
                uint32_t dst = smem_u32(&Bs[s][n*32 + ((c ^ ((n>>1)&3))<<3)]);
                CP16(dst, src);
            }
        }
    };

    loadA(0, 0); loadB(0, 0); CP_COMMIT();

    int s = 0;
    for (int k0 = 0; k0 < K; k0 += 32){
        bool next = (k0 + 32 < K);
        if (next){ loadA(s^1, k0+32); loadB(s^1, k0+32); CP_COMMIT(); }
        if (next) asm volatile("cp.async.wait_group 1;");
        else      asm volatile("cp.async.wait_group 0;");
        __syncthreads();

#pragma unroll
        for (int kp = 0; kp < 2; kp++){
            uint32_t afr[MT][4];
#pragma unroll
            for (int mt = 0; mt < MT; mt++){
                int row = wr*WM + mt*16 + (lane & 15);
                int chunk = kp*2 + (lane >> 4);
                uint32_t addr = smem_u32(&As[s][row*32 + ((chunk ^ ((row>>1)&3))<<3)]);
                LDSM4(afr[mt][0], afr[mt][1], afr[mt][2], afr[mt][3], addr);
            }
            uint32_t bfr[NT][2];
#pragma unroll
            for (int j = 0; j < NT/2; j++){
                uint32_t r0,r1,r2,r3;
                if (!BT){
                    int krow = kp*16 + (lane&7) + ((lane>>3)&1)*8;
                    int chunk = wc*NT + j*2 + (lane >> 4);
                    uint32_t addr = smem_u32(&Bs[s][krow*BN + ((chunk ^ (krow&7))<<3)]);
                    LDSM4T(r0,r1,r2,r3, addr);
                } else {
                    int nrow = wc*WN + j*16 + ((lane>>4)<<3) + (lane&7);
                    int chunk = kp*2 + ((lane>>3)&1);
                    uint32_t addr = smem_u32(&Bs[s][nrow*32 + ((chunk ^ ((nrow>>1)&3))<<3)]);
                    LDSM4(r0,r1,r2,r3, addr);
                }
                bfr[2*j][0]=r0; bfr[2*j][1]=r1; bfr[2*j+1][0]=r2; bfr[2*j+1][1]=r3;
            }
#pragma unroll
            for (int mt = 0; mt < MT; mt++)
#pragma unroll
                for (int nt = 0; nt < NT; nt++)
                    mma_bf16(acc[mt][nt], afr[mt], bfr[nt]);
        }
        __syncthreads();
        s ^= 1;
    }

    int rbase = row0 + wr*WM + (lane>>2);
    int cbase = col0 + wc*WN + (lane&3)*2;
#pragma unroll
    for (int mt=0; mt<MT; mt++){
#pragma unroll
        for (int half=0; half<2; half++){
            int r = rbase + mt*16 + half*8;
#pragma unroll
            for (int nt=0; nt<NT; nt++){
                int c = cbase + nt*8;
                float v0 = acc[mt][nt][half*2+0];
                float v1 = acc[mt][nt][half*2+1];
                if (FLAGS & 8){ v0 *= ATT_SCALE; v1 *= ATT_SCALE; }
                if (FLAGS & 1){ v0 += bias[c]; v1 += bias[c+1]; }
                if (FLAGS & 2){ v0 = gelu_f(v0); v1 = gelu_f(v1); }
                if (FLAGS & 4){
                    const float2 rr = *(const float2*)(R + (size_t)r*ldc + c);
                    v0 += rr.x; v1 += rr.y;
                }
                if (CBF){
                    bf16* C = (bf16*)Cv + (size_t)zb*sCb + (size_t)zh*sCh;
                    *(bf162*)(C + (size_t)r*ldc + c) = __floats2bfloat162_rn(v0, v1);
                } else {
                    float* C = (float*)Cv + (size_t)zb*sCb + (size_t)zh*sCh;
                    float2 o; o.x = v0; o.y = v1;
                    *(float2*)(C + (size_t)r*ldc + c) = o;
                }
            }
        }
    }
}

// ---------------- SE: avg/max pool over tokens (bf16 in) ---------------------
__global__ void pool_kernel(const bf16* __restrict__ x){
    int bb = blockIdx.x / (DIM/128);
    int ch = (blockIdx.x % (DIM/128))*128 + threadIdx.x;
    const bf16* p = x + (size_t)bb*NSEQ*DIM + ch;
    float s = 0.f, m = -1e30f;
    for (int n=0;n<NSEQ;n++){ float v = __bfloat162float(p[(size_t)n*DIM]); s += v; m = fmaxf(m,v); }
    g_pavg[bb*DIM+ch] = s * (1.0f/NSEQ);
    g_pmax[bb*DIM+ch] = m;
}

// ---------------- SE: shared MLP + sigmoid gate ------------------------------
__global__ void semlp_kernel(const float* __restrict__ w1, const float* __restrict__ b1,
                             const float* __restrict__ w2, const float* __restrict__ b2){
    int bb = blockIdx.x;
    int t = threadIdx.x; // 256
    __shared__ float sa[DIM], sm[DIM], ha[SE_H], hm[SE_H];
    sa[t] = g_pavg[bb*DIM+t]; sa[t+256] = g_pavg[bb*DIM+t+256];
    sm[t] = g_pmax[bb*DIM+t]; sm[t+256] = g_pmax[bb*DIM+t+256];
    __syncthreads();
    if (t < SE_H){
        float s = b1[t];
        for (int c=0;c<DIM;c++) s += sa[c]*w1[c*SE_H+t];
        ha[t] = fmaxf(s, 0.f);
    } else if (t < 2*SE_H){
        int j = t - SE_H;
        float s = b1[j];
        for (int c=0;c<DIM;c++) s += sm[c]*w1[c*SE_H+j];
        hm[j] = fmaxf(s, 0.f);
    }
    __syncthreads();
    for (int c=t;c<DIM;c+=256){
        float s = 2.0f*b2[c];
        for (int j=0;j<SE_H;j++) s += (ha[j]+hm[j])*w2[j*DIM+c];
        g_scale[bb*DIM+c] = 1.0f/(1.0f+expf(-s));
    }
}

__global__ void scale_apply_kernel(bf16* __restrict__ xn){
    int bi = blockIdx.x;
    int t = threadIdx.x; // 512
    int bb = bi >> 10;
    size_t idx = (size_t)bi*DIM + t;
    xn[idx] = __float2bfloat16_rn(__bfloat162float(xn[idx]) * g_scale[bb*DIM + t]);
}

// ---------------- Depthwise 3x3 conv + bias + gelu (bf16 in/out) -------------
__global__ void dwconv_kernel(const bf16* __restrict__ h1, const float* __restrict__ w,
                              const float* __restrict__ bias, bf16* __restrict__ out){
    __shared__ float wsh[256*9];
    int m0 = blockIdx.y*256;
    for (int q=threadIdx.x; q<256*9; q+=256) wsh[q] = w[(size_t)m0*9 + q];
    __syncthreads();
    int bi = blockIdx.x;            // b*NSEQ + n
    int m  = m0 + threadIdx.x;
    int bb = bi >> 10, n = bi & 1023;
    int y = n >> 5, x = n & 31;
    float wv[9];
#pragma unroll
    for (int q=0;q<9;q++) wv[q] = wsh[threadIdx.x*9+q];
    float acc = 0.f;
#pragma unroll
    for (int ky=0;ky<3;ky++){
        int yy = y + ky - 1;
        if (yy < 0 || yy > 31) continue;
#pragma unroll
        for (int kx=0;kx<3;kx++){
            int xx = x + kx - 1;
            if (xx < 0 || xx > 31) continue;
            acc += __bfloat162float(h1[((size_t)(bb<<10) + (yy<<5) + xx)*MLPD + m]) * wv[ky*3+kx];
        }
    }
    out[(size_t)bi*MLPD + m] = __float2bfloat16_rn(gelu_f(acc + bias[m]));
}

// ---------------- skip-merge every 2 layers ----------------------------------
__global__ void addres_kernel(){
    size_t i = (size_t)blockIdx.x*256 + threadIdx.x;
    float v = g_x[i] + g_res[i];
    g_x[i] = v; g_res[i] = v;
}

// ---------------- host -------------------------------------------------------
extern "C" void kernel_launch(void* const* d_in, const int* in_sizes, int n_in,
                              void* d_out, int out_size){
    const float* x     = (const float*)d_in[0];
    const float* ln1_g = (const float*)d_in[1];
    const float* ln1_b = (const float*)d_in[2];
    const float* w_qkv = (const float*)d_in[3];
    const float* w_out = (const float*)d_in[4];
    const float* b_out = (const float*)d_in[5];
    const float* ln2_g = (const float*)d_in[6];
    const float* ln2_b = (const float*)d_in[7];
    const float* se_w1 = (const float*)d_in[8];
    const float* se_b1 = (const float*)d_in[9];
    const float* se_w2 = (const float*)d_in[10];
    const float* se_b2 = (const float*)d_in[11];
    const float* w1    = (const float*)d_in[12];
    const float* b1    = (const float*)d_in[13];
    const float* dw_w  = (const float*)d_in[14];
    const float* dw_b  = (const float*)d_in[15];
    const float* w2    = (const float*)d_in[16];
    const float* b2    = (const float*)d_in[17];

    float *px, *pres;
    bf16 *pxn, *pqkv, *pattn, *ph1, *ph2, *pwqkv, *pwout, *pw1, *pw2;
    cudaGetSymbolAddress((void**)&px,    g_x);
    cudaGetSymbolAddress((void**)&pres,  g_res);
    cudaGetSymbolAddress((void**)&pxn,   g_xn_bf);
    cudaGetSymbolAddress((void**)&pqkv,  g_qkv_bf);
    cudaGetSymbolAddress((void**)&pattn, g_attn_bf);
    cudaGetSymbolAddress((void**)&ph1,   g_h1_bf);
    cudaGetSymbolAddress((void**)&ph2,   g_h2_bf);
    cudaGetSymbolAddress((void**)&pwqkv, g_wqkv_bf);
    cudaGetSymbolAddress((void**)&pwout, g_wout_bf);
    cudaGetSymbolAddress((void**)&pw1,   g_w1_bf);
    cudaGetSymbolAddress((void**)&pw2,   g_w2_bf);

    cudaMemcpyAsync(px,   x, (size_t)ROWS*DIM*sizeof(float), cudaMemcpyDeviceToDevice, 0);
    cudaMemcpyAsync(pres, x, (size_t)ROWS*DIM*sizeof(float), cudaMemcpyDeviceToDevice, 0);

    {
        int n;
        n = DEPTH*DIM*3*DIM; f2bf_kernel<<<(n+255)/256,256>>>(w_qkv, pwqkv, n);
        n = DEPTH*DIM*DIM;   f2bf_kernel<<<(n+255)/256,256>>>(w_out, pwout, n);
        n = DEPTH*DIM*MLPD;  f2bf_kernel<<<(n+255)/256,256>>>(w1,    pw1,   n);
        n = DEPTH*MLPD*DIM;  f2bf_kernel<<<(n+255)/256,256>>>(w2,    pw2,   n);
    }

    for (int i=0;i<DEPTH;i++){
        // x -> ln1 -> xn (bf16)
        ln_kernel<<<ROWS,128>>>(px, ln1_g+i*DIM, ln1_b+i*DIM, pxn);
        // qkv = xn @ w_qkv  (bf16 out)
        gemm_bf16<128,128,2,4,0,false,true><<<dim3(3*DIM/128, ROWS/128, 1), 256>>>(
            pxn, pwqkv+(size_t)i*DIM*3*DIM, nullptr, nullptr, pqkv,
            ROWS, 3*DIM, DIM, DIM, 3*DIM, 3*DIM, 0,0,0,0,0,0, 1);
        // fused attention: scores + softmax + PV in one kernel
        flash_attn_kernel<<<dim3(NSEQ/128, BB*HEADS), 256>>>(pqkv, pattn);
        // x = attn @ w_out + b_out + x  (fp32 out)
        gemm_bf16<128,128,2,4,5,false,false><<<dim3(DIM/128, ROWS/128, 1), 256>>>(
            pattn, pwout+(size_t)i*DIM*DIM, b_out+i*DIM, px, px,
            ROWS, DIM, DIM, DIM, DIM, DIM, 0,0,0,0,0,0, 1);
        // x -> ln2 -> xn (bf16)
        ln_kernel<<<ROWS,128>>>(px, ln2_g+i*DIM, ln2_b+i*DIM, pxn);
        // SE gate
        pool_kernel<<<BB*(DIM/128),128>>>(pxn);
        semlp_kernel<<<BB,256>>>(se_w1+(size_t)i*DIM*SE_H, se_b1+i*SE_H,
                                 se_w2+(size_t)i*SE_H*DIM, se_b2+i*DIM);
        scale_apply_kernel<<<ROWS,512>>>(pxn);
        // h1 = gelu(xn @ w1 + b1)  (bf16 out)
        gemm_bf16<128,128,2,4,3,false,true><<<dim3(MLPD/128, ROWS/128, 1),256>>>(
            pxn, pw1+(size_t)i*DIM*MLPD, b1+i*MLPD, nullptr, ph1,
            ROWS, MLPD, DIM, DIM, MLPD, MLPD, 0,0,0,0,0,0, 1);
        // h2 = gelu(dwconv3x3(h1) + dw_b)
        dwconv_kernel<<<dim3(ROWS, MLPD/256), 256>>>(ph1, dw_w+(size_t)i*MLPD*9, dw_b+i*MLPD, ph2);
        // x = gelu(h2 @ w2 + b2) + x  (fp32 out)
        gemm_bf16<128,128,2,4,7,false,false><<<dim3(DIM/128, ROWS/128, 1),256>>>(
            ph2, pw2+(size_t)i*MLPD*DIM, b2+i*DIM, px, px,
            ROWS, DIM, MLPD, MLPD, DIM, DIM, 0,0,0,0,0,0, 1);
        // skip merge every 2 layers
        if ((i&1)==1) addres_kernel<<<ROWS*DIM/256, 256>>>();
    }
    cudaMemcpyAsync(d_out, px, (size_t)ROWS*DIM*sizeof(float), cudaMemcpyDeviceToDevice, 0);
}

// round 9
// speedup vs baseline: 5.2495x; 1.0143x over previous
#include <cuda_runtime.h>
#include <cuda_bf16.h>
#include <math.h>
#include <stdint.h>

#define DEPTH 4
#define DIM 512
#define HEADS 8
#define HD 64
#define MLPD 2048
#define SE_H 32
#define BB 8
#define NSEQ 1024
#define ROWS (BB*NSEQ)
#define EPS 1e-5f
#define ATT_SCALE 0.04419417382415922f  /* 512^-0.5 */

typedef __nv_bfloat16 bf16;
typedef __nv_bfloat162 bf162;

// ---------------- scratch (static device memory, no allocs) ----------------
__device__ float g_x[ROWS*DIM];
__device__ float g_res[ROWS*DIM];
__device__ float g_pavg[BB*DIM];
__device__ float g_pmax[BB*DIM];
__device__ float g_scale[BB*DIM];

__device__ bf16 g_xn_bf[ROWS*DIM];
__device__ bf16 g_qkv_bf[ROWS*3*DIM];
__device__ bf16 g_attn_bf[ROWS*DIM];
__device__ bf16 g_h1_bf[ROWS*MLPD];
__device__ bf16 g_h2_bf[ROWS*MLPD];

__device__ bf16 g_wqkv_bf[DEPTH*DIM*3*DIM];
__device__ bf16 g_wout_bf[DEPTH*DIM*DIM];
__device__ bf16 g_w1_bf[DEPTH*DIM*MLPD];
__device__ bf16 g_w2_bf[DEPTH*MLPD*DIM];

__device__ __forceinline__ float gelu_f(float v){
    return 0.5f * v * (1.0f + erff(v * 0.7071067811865476f));
}
__device__ __forceinline__ uint32_t smem_u32(const void* p){
    return (uint32_t)__cvta_generic_to_shared(p);
}
__device__ __forceinline__ void mma_bf16(float* d, const uint32_t* a, const uint32_t* b){
    asm volatile("mma.sync.aligned.m16n8k16.row.col.f32.bf16.bf16.f32 "
        "{%0,%1,%2,%3}, {%4,%5,%6,%7}, {%8,%9}, {%0,%1,%2,%3};"
        : "+f"(d[0]),"+f"(d[1]),"+f"(d[2]),"+f"(d[3])
        : "r"(a[0]),"r"(a[1]),"r"(a[2]),"r"(a[3]), "r"(b[0]),"r"(b[1]));
}
#define LDSM4(r0,r1,r2,r3,addr) \
    asm volatile("ldmatrix.sync.aligned.m8n8.x4.shared.b16 {%0,%1,%2,%3}, [%4];" \
        : "=r"(r0),"=r"(r1),"=r"(r2),"=r"(r3) : "r"(addr))
#define LDSM4T(r0,r1,r2,r3,addr) \
    asm volatile("ldmatrix.sync.aligned.m8n8.x4.trans.shared.b16 {%0,%1,%2,%3}, [%4];" \
        : "=r"(r0),"=r"(r1),"=r"(r2),"=r"(r3) : "r"(addr))
#define CP16(dst,src) \
    asm volatile("cp.async.cg.shared.global [%0], [%1], 16;" :: "r"(dst), "l"(src))
#define CP_COMMIT() asm volatile("cp.async.commit_group;")

// ---------------- fp32 -> bf16 weight convert (vectorized) -------------------
__global__ void f2bf_kernel(const float4* __restrict__ in, uint2* __restrict__ out, int n4){
    int i = blockIdx.x*256 + threadIdx.x;
    if (i < n4){
        float4 v = in[i];
        bf162 a = __floats2bfloat162_rn(v.x, v.y);
        bf162 b = __floats2bfloat162_rn(v.z, v.w);
        uint2 o; o.x = *(uint32_t*)&a; o.y = *(uint32_t*)&b;
        out[i] = o;
    }
}

// ---------------- LayerNorm (fp32 in -> bf16 out) ---------------------------
__global__ void ln_kernel(const float* __restrict__ x, const float* __restrict__ g,
                          const float* __restrict__ bta, bf16* __restrict__ o){
    int row = blockIdx.x;
    int t = threadIdx.x;
    const float* xr = x + (size_t)row * DIM;
    float v[4];
    float s = 0.f;
#pragma unroll
    for (int i=0;i<4;i++){ v[i] = xr[t + 128*i]; s += v[i]; }
    __shared__ float sh[32];
    for (int off=16;off>0;off>>=1) s += __shfl_down_sync(0xffffffffu, s, off);
    if ((t&31)==0) sh[t>>5] = s;
    __syncthreads();
    if (t < 32){
        float r = (t < 4) ? sh[t] : 0.f;
        for (int off=2;off>0;off>>=1) r += __shfl_down_sync(0xffffffffu, r, off);
        if (t==0) sh[0] = r;
    }
    __syncthreads();
    float mean = sh[0] * (1.0f/DIM);
    __syncthreads();
    float sq = 0.f;
#pragma unroll
    for (int i=0;i<4;i++){ v[i] -= mean; sq += v[i]*v[i]; }
    for (int off=16;off>0;off>>=1) sq += __shfl_down_sync(0xffffffffu, sq, off);
    if ((t&31)==0) sh[t>>5] = sq;
    __syncthreads();
    if (t < 32){
        float r = (t < 4) ? sh[t] : 0.f;
        for (int off=2;off>0;off>>=1) r += __shfl_down_sync(0xffffffffu, r, off);
        if (t==0) sh[0] = r;
    }
    __syncthreads();
    float rstd = rsqrtf(sh[0]*(1.0f/DIM) + EPS);
    bf16* orow = o + (size_t)row*DIM;
#pragma unroll
    for (int i=0;i<4;i++){
        int c = t + 128*i;
        orow[c] = __float2bfloat16_rn(v[i]*rstd*g[c] + bta[c]);
    }
}

// ---------------- Flash attention: fused QK^T + softmax + PV -----------------
// grid (NSEQ/128, BB*HEADS), block 256 (8 warps, each owns 16 Q rows)
__global__ void __launch_bounds__(256)
flash_attn_kernel(const bf16* __restrict__ qkv, bf16* __restrict__ out){
    int bh = blockIdx.y;
    int b = bh >> 3, h = bh & 7;
    int i0 = blockIdx.x * 128;
    const bf16* base = qkv + (size_t)b*NSEQ*3*DIM;
    const bf16* Qp = base + (size_t)h*HD;
    const bf16* Kp = base + DIM + (size_t)h*HD;
    const bf16* Vp = base + 2*DIM + (size_t)h*HD;

    __shared__ __align__(16) bf16 Qs[128*64];
    __shared__ __align__(16) bf16 Ks[2][64*64];
    __shared__ __align__(16) bf16 Vs[2][64*64];

    int t = threadIdx.x, warp = t >> 5, lane = t & 31;

    // Q tile -> smem (swizzled)
#pragma unroll
    for (int i = t; i < 128*8; i += 256){
        int r = i >> 3, c = i & 7;
        CP16(smem_u32(&Qs[r*64 + ((c ^ (r&7))<<3)]), Qp + (size_t)(i0+r)*(3*DIM) + c*8);
    }
    auto loadKV = [&](int s, int j0){
#pragma unroll
        for (int i = t; i < 64*8; i += 256){
            int r = i >> 3, c = i & 7;
            CP16(smem_u32(&Ks[s][r*64 + ((c ^ (r&7))<<3)]), Kp + (size_t)(j0+r)*(3*DIM) + c*8);
        }
#pragma unroll
        for (int i = t; i < 64*8; i += 256){
            int r = i >> 3, c = i & 7;
            CP16(smem_u32(&Vs[s][r*64 + ((c ^ (r&7))<<3)]), Vp + (size_t)(j0+r)*(3*DIM) + c*8);
        }
    };
    loadKV(0, 0);
    CP_COMMIT();
    asm volatile("cp.async.wait_group 0;");
    __syncthreads();

    // Q fragments (held in registers for the whole kernel)
    uint32_t qf[4][4];
#pragma unroll
    for (int kp=0;kp<4;kp++){
        int row = warp*16 + (lane & 15);
        int chunk = kp*2 + (lane >> 4);
        uint32_t addr = smem_u32(&Qs[row*64 + ((chunk ^ (row&7))<<3)]);
        LDSM4(qf[kp][0], qf[kp][1], qf[kp][2], qf[kp][3], addr);
    }

    float of[8][4];
#pragma unroll
    for (int nt=0;nt<8;nt++)
#pragma unroll
        for (int q=0;q<4;q++) of[nt][q] = 0.f;
    float m0 = -1e30f, m1 = -1e30f, l0 = 0.f, l1 = 0.f;

    int s = 0;
    for (int it=0; it<16; it++){
        if (it < 15){ loadKV(s^1, (it+1)*64); CP_COMMIT(); }

        // ---- S = Q @ K^T (this 64-key tile) ----
        float sacc[8][4];
#pragma unroll
        for (int nt=0;nt<8;nt++)
#pragma unroll
            for (int q=0;q<4;q++) sacc[nt][q] = 0.f;
#pragma unroll
        for (int kp=0;kp<4;kp++){
            uint32_t bfr[8][2];
#pragma unroll
            for (int j=0;j<4;j++){
                int nrow = j*16 + ((lane>>4)<<3) + (lane&7);
                int chunk = kp*2 + ((lane>>3)&1);
                uint32_t addr = smem_u32(&Ks[s][nrow*64 + ((chunk ^ (nrow&7))<<3)]);
                uint32_t r0,r1,r2,r3; LDSM4(r0,r1,r2,r3, addr);
                bfr[2*j][0]=r0; bfr[2*j][1]=r1; bfr[2*j+1][0]=r2; bfr[2*j+1][1]=r3;
            }
#pragma unroll
            for (int nt=0;nt<8;nt++) mma_bf16(sacc[nt], qf[kp], bfr[nt]);
        }

        // ---- online softmax (rows r = warp*16 + lane/4 and r+8) ----
        float tm0 = -1e30f, tm1 = -1e30f;
#pragma unroll
        for (int nt=0;nt<8;nt++){
            sacc[nt][0] *= ATT_SCALE; sacc[nt][1] *= ATT_SCALE;
            sacc[nt][2] *= ATT_SCALE; sacc[nt][3] *= ATT_SCALE;
            tm0 = fmaxf(tm0, fmaxf(sacc[nt][0], sacc[nt][1]));
            tm1 = fmaxf(tm1, fmaxf(sacc[nt][2], sacc[nt][3]));
        }
        tm0 = fmaxf(tm0, __shfl_xor_sync(0xffffffffu, tm0, 1));
        tm0 = fmaxf(tm0, __shfl_xor_sync(0xffffffffu, tm0, 2));
        tm1 = fmaxf(tm1, __shfl_xor_sync(0xffffffffu, tm1, 1));
        tm1 = fmaxf(tm1, __shfl_xor_sync(0xffffffffu, tm1, 2));
        float mn0 = fmaxf(m0, tm0), mn1 = fmaxf(m1, tm1);
        float a0 = __expf(m0 - mn0), a1 = __expf(m1 - mn1);
        m0 = mn0; m1 = mn1;
        float rs0 = 0.f, rs1 = 0.f;
#pragma unroll
        for (int nt=0;nt<8;nt++){
            sacc[nt][0] = __expf(sacc[nt][0] - m0);
            sacc[nt][1] = __expf(sacc[nt][1] - m0);
            sacc[nt][2] = __expf(sacc[nt][2] - m1);
            sacc[nt][3] = __expf(sacc[nt][3] - m1);
            rs0 += sacc[nt][0] + sacc[nt][1];
            rs1 += sacc[nt][2] + sacc[nt][3];
        }
        rs0 += __shfl_xor_sync(0xffffffffu, rs0, 1);
        rs0 += __shfl_xor_sync(0xffffffffu, rs0, 2);
        rs1 += __shfl_xor_sync(0xffffffffu, rs1, 1);
        rs1 += __shfl_xor_sync(0xffffffffu, rs1, 2);
        l0 = l0*a0 + rs0;
        l1 = l1*a1 + rs1;
#pragma unroll
        for (int nt=0;nt<8;nt++){
            of[nt][0] *= a0; of[nt][1] *= a0;
            of[nt][2] *= a1; of[nt][3] *= a1;
        }

        // ---- pack P into A-fragments (acc layout == A-frag layout) ----
        uint32_t pf[4][4];
#pragma unroll
        for (int kc=0;kc<4;kc++){
            bf162 p0 = __floats2bfloat162_rn(sacc[2*kc  ][0], sacc[2*kc  ][1]);
            bf162 p1 = __floats2bfloat162_rn(sacc[2*kc  ][2], sacc[2*kc  ][3]);
            bf162 p2 = __floats2bfloat162_rn(sacc[2*kc+1][0], sacc[2*kc+1][1]);
            bf162 p3 = __floats2bfloat162_rn(sacc[2*kc+1][2], sacc[2*kc+1][3]);
            pf[kc][0] = *(uint32_t*)&p0;
            pf[kc][1] = *(uint32_t*)&p1;
            pf[kc][2] = *(uint32_t*)&p2;
            pf[kc][3] = *(uint32_t*)&p3;
        }

        // ---- O += P @ V ----
#pragma unroll
        for (int kp=0;kp<4;kp++){
            uint32_t vfr[8][2];
#pragma unroll
            for (int j=0;j<4;j++){
                int krow = kp*16 + (lane&7) + ((lane>>3)&1)*8;
                int chunk = j*2 + (lane>>4);
                uint32_t addr = smem_u32(&Vs[s][krow*64 + ((chunk ^ (krow&7))<<3)]);
                uint32_t r0,r1,r2,r3; LDSM4T(r0,r1,r2,r3, addr);
                vfr[2*j][0]=r0; vfr[2*j][1]=r1; vfr[2*j+1][0]=r2; vfr[2*j+1][1]=r3;
            }
#pragma unroll
            for (int nt=0;nt<8;nt++) mma_bf16(of[nt], pf[kp], vfr[nt]);
        }

        if (it < 15) asm volatile("cp.async.wait_group 0;");
        __syncthreads();
        s ^= 1;
    }

    // ---- normalize and store (merged-head layout [b*n, DIM]) ----
    float inv0 = 1.0f / l0, inv1 = 1.0f / l1;
    int r = warp*16 + (lane>>2);
    bf16* op = out + ((size_t)(b*NSEQ + i0 + r))*DIM + h*HD + (lane&3)*2;
#pragma unroll
    for (int nt=0;nt<8;nt++){
        bf162 o0 = __floats2bfloat162_rn(of[nt][0]*inv0, of[nt][1]*inv0);
        bf162 o1 = __floats2bfloat162_rn(of[nt][2]*inv1, of[nt][3]*inv1);
        *(bf162*)(op + nt*8)            = o0;
        *(bf162*)(op + 8*DIM + nt*8)    = o1;
    }
}

// ---------------- bf16 tensor-core GEMM: 3-stage cp.async pipeline ----------
// C = A @ B; A row-major [M,K]; B: [K,N] row-major (NN) or [N,K] row-major (BT)
// FLAGS: 1=+bias, 2=gelu, 4=+residual R(fp32,ldc), 8=*ATT_SCALE,
//        16=skip-merge (v += R2; R2 = v). CBF: C bf16.
template<int BM,int BN,int WARPS_M,int WARPS_N,int FLAGS,bool BT,bool CBF>
__global__ void __launch_bounds__(WARPS_M*WARPS_N*32, 2)
gemm_bf16(const bf16* __restrict__ A, const bf16* __restrict__ B,
          const float* __restrict__ bias, const float* __restrict__ R,
          float* __restrict__ R2, void* Cv,
          int M, int N, int K, int lda, int ldb, int ldc,
          long sAb, long sAh, long sBb, long sBh, long sCb, long sCh, int H)
{
    constexpr int THREADS = WARPS_M*WARPS_N*32;
    constexpr int WM = BM/WARPS_M, WN = BN/WARPS_N;
    constexpr int MT = WM/16, NT = WN/8;
    constexpr int CH_B = BN/8;

    __shared__ __align__(16) bf16 As[3][BM*32];
    __shared__ __align__(16) bf16 Bs[3][32*BN];

    int z = blockIdx.z;
    int zb = z / H, zh = z % H;
    A += (size_t)zb*sAb + (size_t)zh*sAh;
    B += (size_t)zb*sBb + (size_t)zh*sBh;

    int t = threadIdx.x;
    int warp = t >> 5, lane = t & 31;
    int wr = warp % WARPS_M, wc = warp / WARPS_M;
    int row0 = blockIdx.y * BM;
    int col0 = blockIdx.x * BN;

    float acc[MT][NT][4];
#pragma unroll
    for (int i=0;i<MT;i++)
#pragma unroll
        for (int j=0;j<NT;j++)
#pragma unroll
            for (int q=0;q<4;q++) acc[i][j][q]=0.f;

    auto loadA = [&](int s, int k0){
#pragma unroll
        for (int i = t; i < BM*4; i += THREADS){
            int r = i >> 2, c = i & 3;
            const bf16* src = A + (size_t)(row0+r)*lda + k0 + c*8;
            uint32_t dst = smem_u32(&As[s][r*32 + ((c ^ ((r>>1)&3))<<3)]);
            CP16(dst, src);
        }
    };
    auto loadB = [&](int s, int k0){
        if (!BT){
#pragma unroll
            for (int i = t; i < 32*CH_B; i += THREADS){
                int r = i / CH_B, c = i % CH_B;
                const bf16* src = B + (size_t)(k0+r)*ldb + col0 + c*8;
                uint32_t dst = smem_u32(&Bs[s][r*BN + ((c ^ (r&7))<<3)]);
                CP16(dst, src);
            }
        } else {
#pragma unroll
            for (int i = t; i < BN*4; i += THREADS){
                int n = i >> 2, c = i & 3;
                const bf16* src = B + (size_t)(col0+n)*ldb + k0 + c*8;
                uint32_t dst = smem_u32(&Bs[s][n*32 + ((c ^ ((n>>1)&3))<<3)]);
                CP16(dst, src);
            }
        }
    };

    const int niter = K/32;
    loadA(0, 0);  loadB(0, 0);  CP_COMMIT();
    loadA(1, 32); loadB(1, 32); CP_COMMIT();

    for (int i = 0; i < niter; i++){
        // stage i's group is complete when at most 1 (the newest) remains pending
        if (i + 1 < niter) asm volatile("cp.async.wait_group 1;");
        else               asm volatile("cp.async.wait_group 0;");
        __syncthreads();
        if (i + 2 < niter){
            int s2 = (i+2) % 3;
            loadA(s2, (i+2)*32); loadB(s2, (i+2)*32); CP_COMMIT();
        }
        int s = i % 3;

#pragma unroll
        for (int kp = 0; kp < 2; kp++){
            uint32_t afr[MT][4];
#pragma unroll
            for (int mt = 0; mt < MT; mt++){
                int row = wr*WM + mt*16 + (lane & 15);
                int chunk = kp*2 + (lane >> 4);
                uint32_t addr = smem_u32(&As[s][row*32 + ((chunk ^ ((row>>1)&3))<<3)]);
                LDSM4(afr[mt][0], afr[mt][1], afr[mt][2], afr[mt][3], addr);
            }
            uint32_t bfr[NT][2];
#pragma unroll
            for (int j = 0; j < NT/2; j++){
                uint32_t r0,r1,r2,r3;
                if (!BT){
                    int krow = kp*16 + (lane&7) + ((lane>>3)&1)*8;
                    int chunk = wc*NT + j*2 + (lane >> 4);
                    uint32_t addr = smem_u32(&Bs[s][krow*BN + ((chunk ^ (krow&7))<<3)]);
                    LDSM4T(r0,r1,r2,r3, addr);
                } else {
                    int nrow = wc*WN + j*16 + ((lane>>4)<<3) + (lane&7);
                    int chunk = kp*2 + ((lane>>3)&1);
                    uint32_t addr = smem_u32(&Bs[s][nrow*32 + ((chunk ^ ((nrow>>1)&3))<<3)]);
                    LDSM4(r0,r1,r2,r3, addr);
                }
                bfr[2*j][0]=r0; bfr[2*j][1]=r1; bfr[2*j+1][0]=r2; bfr[2*j+1][1]=r3;
            }
#pragma unroll
            for (int mt = 0; mt < MT; mt++)
#pragma unroll
                for (int nt = 0; nt < NT; nt++)
                    mma_bf16(acc[mt][nt], afr[mt], bfr[nt]);
        }
    }

    // ---- epilogue ----
    int rbase = row0 + wr*WM + (lane>>2);
    int cbase = col0 + wc*WN + (lane&3)*2;
#pragma unroll
    for (int mt=0; mt<MT; mt++){
#pragma unroll
        for (int half=0; half<2; half++){
            int r = rbase + mt*16 + half*8;
#pragma unroll
            for (int nt=0; nt<NT; nt++){
                int c = cbase + nt*8;
                float v0 = acc[mt][nt][half*2+0];
                float v1 = acc[mt][nt][half*2+1];
                if (FLAGS & 8){ v0 *= ATT_SCALE; v1 *= ATT_SCALE; }
                if (FLAGS & 1){ v0 += bias[c]; v1 += bias[c+1]; }
                if (FLAGS & 2){ v0 = gelu_f(v0); v1 = gelu_f(v1); }
                if (FLAGS & 4){
                    const float2 rr = *(const float2*)(R + (size_t)r*ldc + c);
                    v0 += rr.x; v1 += rr.y;
                }
                if (FLAGS & 16){
                    float2 rr2 = *(float2*)(R2 + (size_t)r*ldc + c);
                    v0 += rr2.x; v1 += rr2.y;
                    float2 w; w.x = v0; w.y = v1;
                    *(float2*)(R2 + (size_t)r*ldc + c) = w;
                }
                if (CBF){
                    bf16* C = (bf16*)Cv + (size_t)zb*sCb + (size_t)zh*sCh;
                    *(bf162*)(C + (size_t)r*ldc + c) = __floats2bfloat162_rn(v0, v1);
                } else {
                    float* C = (float*)Cv + (size_t)zb*sCb + (size_t)zh*sCh;
                    float2 o; o.x = v0; o.y = v1;
                    *(float2*)(C + (size_t)r*ldc + c) = o;
                }
            }
        }
    }
}

// ---------------- SE: avg/max pool over tokens (bf16 in) ---------------------
__global__ void pool_kernel(const bf16* __restrict__ x){
    int bb = blockIdx.x / (DIM/128);
    int ch = (blockIdx.x % (DIM/128))*128 + threadIdx.x;
    const bf16* p = x + (size_t)bb*NSEQ*DIM + ch;
    float s = 0.f, m = -1e30f;
    for (int n=0;n<NSEQ;n++){ float v = __bfloat162float(p[(size_t)n*DIM]); s += v; m = fmaxf(m,v); }
    g_pavg[bb*DIM+ch] = s * (1.0f/NSEQ);
    g_pmax[bb*DIM+ch] = m;
}

// ---------------- SE: shared MLP + sigmoid gate ------------------------------
__global__ void semlp_kernel(const float* __restrict__ w1, const float* __restrict__ b1,
                             const float* __restrict__ w2, const float* __restrict__ b2){
    int bb = blockIdx.x;
    int t = threadIdx.x; // 256
    __shared__ float sa[DIM], sm[DIM], ha[SE_H], hm[SE_H];
    sa[t] = g_pavg[bb*DIM+t]; sa[t+256] = g_pavg[bb*DIM+t+256];
    sm[t] = g_pmax[bb*DIM+t]; sm[t+256] = g_pmax[bb*DIM+t+256];
    __syncthreads();
    if (t < SE_H){
        float s = b1[t];
        for (int c=0;c<DIM;c++) s += sa[c]*w1[c*SE_H+t];
        ha[t] = fmaxf(s, 0.f);
    } else if (t < 2*SE_H){
        int j = t - SE_H;
        float s = b1[j];
        for (int c=0;c<DIM;c++) s += sm[c]*w1[c*SE_H+j];
        hm[j] = fmaxf(s, 0.f);
    }
    __syncthreads();
    for (int c=t;c<DIM;c+=256){
        float s = 2.0f*b2[c];
        for (int j=0;j<SE_H;j++) s += (ha[j]+hm[j])*w2[j*DIM+c];
        g_scale[bb*DIM+c] = 1.0f/(1.0f+expf(-s));
    }
}

__global__ void scale_apply_kernel(bf16* __restrict__ xn){
    int bi = blockIdx.x;
    int t = threadIdx.x; // 512
    int bb = bi >> 10;
    size_t idx = (size_t)bi*DIM + t;
    xn[idx] = __float2bfloat16_rn(__bfloat162float(xn[idx]) * g_scale[bb*DIM + t]);
}

// ---------------- Depthwise 3x3 conv + bias + gelu (bf16, 2 ch/thread) -------
__global__ void dwconv_kernel(const bf16* __restrict__ h1, const float* __restrict__ w,
                              const float* __restrict__ bias, bf16* __restrict__ out){
    __shared__ float wsh[512*9];
    int m0 = blockIdx.y*512;
    for (int q=threadIdx.x; q<512*9; q+=256) wsh[q] = w[(size_t)m0*9 + q];
    __syncthreads();
    int bi = blockIdx.x;            // b*NSEQ + n
    int m  = m0 + 2*threadIdx.x;    // pair of channels
    int bb = bi >> 10, n = bi & 1023;
    int y = n >> 5, x = n & 31;
    float wv0[9], wv1[9];
#pragma unroll
    for (int q=0;q<9;q++){ wv0[q] = wsh[(2*threadIdx.x)*9+q]; wv1[q] = wsh[(2*threadIdx.x+1)*9+q]; }
    float acc0 = 0.f, acc1 = 0.f;
#pragma unroll
    for (int ky=0;ky<3;ky++){
        int yy = y + ky - 1;
        if (yy < 0 || yy > 31) continue;
#pragma unroll
        for (int kx=0;kx<3;kx++){
            int xx = x + kx - 1;
            if (xx < 0 || xx > 31) continue;
            bf162 hv = *(const bf162*)(h1 + ((size_t)(bb<<10) + (yy<<5) + xx)*MLPD + m);
            float2 f = __bfloat1622float2(hv);
            acc0 += f.x * wv0[ky*3+kx];
            acc1 += f.y * wv1[ky*3+kx];
        }
    }
    bf162 o = __floats2bfloat162_rn(gelu_f(acc0 + bias[m]), gelu_f(acc1 + bias[m+1]));
    *(bf162*)(out + (size_t)bi*MLPD + m) = o;
}

// ---------------- host -------------------------------------------------------
extern "C" void kernel_launch(void* const* d_in, const int* in_sizes, int n_in,
                              void* d_out, int out_size){
    const float* x     = (const float*)d_in[0];
    const float* ln1_g = (const float*)d_in[1];
    const float* ln1_b = (const float*)d_in[2];
    const float* w_qkv = (const float*)d_in[3];
    const float* w_out = (const float*)d_in[4];
    const float* b_out = (const float*)d_in[5];
    const float* ln2_g = (const float*)d_in[6];
    const float* ln2_b = (const float*)d_in[7];
    const float* se_w1 = (const float*)d_in[8];
    const float* se_b1 = (const float*)d_in[9];
    const float* se_w2 = (const float*)d_in[10];
    const float* se_b2 = (const float*)d_in[11];
    const float* w1    = (const float*)d_in[12];
    const float* b1    = (const float*)d_in[13];
    const float* dw_w  = (const float*)d_in[14];
    const float* dw_b  = (const float*)d_in[15];
    const float* w2    = (const float*)d_in[16];
    const float* b2    = (const float*)d_in[17];

    float *px, *pres;
    bf16 *pxn, *pqkv, *pattn, *ph1, *ph2, *pwqkv, *pwout, *pw1, *pw2;
    cudaGetSymbolAddress((void**)&px,    g_x);
    cudaGetSymbolAddress((void**)&pres,  g_res);
    cudaGetSymbolAddress((void**)&pxn,   g_xn_bf);
    cudaGetSymbolAddress((void**)&pqkv,  g_qkv_bf);
    cudaGetSymbolAddress((void**)&pattn, g_attn_bf);
    cudaGetSymbolAddress((void**)&ph1,   g_h1_bf);
    cudaGetSymbolAddress((void**)&ph2,   g_h2_bf);
    cudaGetSymbolAddress((void**)&pwqkv, g_wqkv_bf);
    cudaGetSymbolAddress((void**)&pwout, g_wout_bf);
    cudaGetSymbolAddress((void**)&pw1,   g_w1_bf);
    cudaGetSymbolAddress((void**)&pw2,   g_w2_bf);

    cudaMemcpyAsync(px,   x, (size_t)ROWS*DIM*sizeof(float), cudaMemcpyDeviceToDevice, 0);
    cudaMemcpyAsync(pres, x, (size_t)ROWS*DIM*sizeof(float), cudaMemcpyDeviceToDevice, 0);

    {
        int n;
        n = DEPTH*DIM*3*DIM/4; f2bf_kernel<<<(n+255)/256,256>>>((const float4*)w_qkv, (uint2*)pwqkv, n);
        n = DEPTH*DIM*DIM/4;   f2bf_kernel<<<(n+255)/256,256>>>((const float4*)w_out, (uint2*)pwout, n);
        n = DEPTH*DIM*MLPD/4;  f2bf_kernel<<<(n+255)/256,256>>>((const float4*)w1,    (uint2*)pw1,   n);
        n = DEPTH*MLPD*DIM/4;  f2bf_kernel<<<(n+255)/256,256>>>((const float4*)w2,    (uint2*)pw2,   n);
    }

    for (int i=0;i<DEPTH;i++){
        // x -> ln1 -> xn (bf16)
        ln_kernel<<<ROWS,128>>>(px, ln1_g+i*DIM, ln1_b+i*DIM, pxn);
        // qkv = xn @ w_qkv  (bf16 out)
        gemm_bf16<128,128,2,4,0,false,true><<<dim3(3*DIM/128, ROWS/128, 1), 256>>>(
            pxn, pwqkv+(size_t)i*DIM*3*DIM, nullptr, nullptr, nullptr, pqkv,
            ROWS, 3*DIM, DIM, DIM, 3*DIM, 3*DIM, 0,0,0,0,0,0, 1);
        // fused attention: scores + softmax + PV in one kernel
        flash_attn_kernel<<<dim3(NSEQ/128, BB*HEADS), 256>>>(pqkv, pattn);
        // x = attn @ w_out + b_out + x  (fp32 out)
        gemm_bf16<128,128,2,4,5,false,false><<<dim3(DIM/128, ROWS/128, 1), 256>>>(
            pattn, pwout+(size_t)i*DIM*DIM, b_out+i*DIM, px, nullptr, px,
            ROWS, DIM, DIM, DIM, DIM, DIM, 0,0,0,0,0,0, 1);
        // x -> ln2 -> xn (bf16)
        ln_kernel<<<ROWS,128>>>(px, ln2_g+i*DIM, ln2_b+i*DIM, pxn);
        // SE gate
        pool_kernel<<<BB*(DIM/128),128>>>(pxn);
        semlp_kernel<<<BB,256>>>(se_w1+(size_t)i*DIM*SE_H, se_b1+i*SE_H,
                                 se_w2+(size_t)i*SE_H*DIM, se_b2+i*DIM);
        scale_apply_kernel<<<ROWS,512>>>(pxn);
        // h1 = gelu(xn @ w1 + b1)  (bf16 out)
        gemm_bf16<128,128,2,4,3,false,true><<<dim3(MLPD/128, ROWS/128, 1),256>>>(
            pxn, pw1+(size_t)i*DIM*MLPD, b1+i*MLPD, nullptr, nullptr, ph1,
            ROWS, MLPD, DIM, DIM, MLPD, MLPD, 0,0,0,0,0,0, 1);
        // h2 = gelu(dwconv3x3(h1) + dw_b)
        dwconv_kernel<<<dim3(ROWS, MLPD/512), 256>>>(ph1, dw_w+(size_t)i*MLPD*9, dw_b+i*MLPD, ph2);
        // x = gelu(h2 @ w2 + b2) + x  (fp32 out); odd layers also merge skip
        if ((i&1)==1){
            gemm_bf16<128,128,2,4,23,false,false><<<dim3(DIM/128, ROWS/128, 1),256>>>(
                ph2, pw2+(size_t)i*MLPD*DIM, b2+i*DIM, px, pres, px,
                ROWS, DIM, MLPD, MLPD, DIM, DIM, 0,0,0,0,0,0, 1);
        } else {
            gemm_bf16<128,128,2,4,7,false,false><<<dim3(DIM/128, ROWS/128, 1),256>>>(
                ph2, pw2+(size_t)i*MLPD*DIM, b2+i*DIM, px, nullptr, px,
                ROWS, DIM, MLPD, MLPD, DIM, DIM, 0,0,0,0,0,0, 1);
        }
    }
    cudaMemcpyAsync(d_out, px, (size_t)ROWS*DIM*sizeof(float), cudaMemcpyDeviceToDevice, 0);
}